// round 12
// baseline (speedup 1.0000x reference)
#include <cuda_runtime.h>
#include <cuda_bf16.h>
#include <cstdint>

// Problem constants
#define BB 2
#define CC 256
#define HW 16384
#define SS 256
#define TT 128
#define NH 8
#define DH 32
#define SCALE 0.17677669529663689f   // 32^-0.5
#define LN_EPS 1e-5f

typedef unsigned long long u64;

// warp-level bf16 MMA, m16n8k16, fp32 accumulate (baseline PTX)
#define MMA_BF16(c0,c1,c2,c3, a0,a1,a2,a3, b0,b1) \
    asm("mma.sync.aligned.m16n8k16.row.col.f32.bf16.bf16.f32 " \
        "{%0,%1,%2,%3}, {%4,%5,%6,%7}, {%8,%9}, {%0,%1,%2,%3};" \
        : "+f"(c0), "+f"(c1), "+f"(c2), "+f"(c3) \
        : "r"(a0), "r"(a1), "r"(a2), "r"(a3), "r"(b0), "r"(b1))

__device__ __forceinline__ uint32_t pk2(__nv_bfloat16 a, __nv_bfloat16 b) {
    unsigned short ua = *(unsigned short*)&a, ub = *(unsigned short*)&b;
    return (uint32_t)ua | ((uint32_t)ub << 16);
}

// ---------------- scratch (device globals; no allocation allowed) ----------------
__device__ __nv_bfloat16 g_xh[(size_t)BB * HW * CC];  // LN output hi bf16, [m][c]
__device__ __nv_bfloat16 g_xl[(size_t)BB * HW * CC];  // LN output lo bf16
__device__ __nv_bfloat16 g_wh[3 * CC * CC];           // W hi bf16 (wq pre-scaled)
__device__ __nv_bfloat16 g_wl[3 * CC * CC];
__device__ __nv_bfloat16 g_qh[(size_t)BB * HW * CC];  // projections, split bf16 [m][o]
__device__ __nv_bfloat16 g_ql[(size_t)BB * HW * CC];
__device__ __nv_bfloat16 g_kh[(size_t)BB * HW * CC];
__device__ __nv_bfloat16 g_kl[(size_t)BB * HW * CC];
__device__ __nv_bfloat16 g_vh[(size_t)BB * HW * CC];
__device__ __nv_bfloat16 g_vl[(size_t)BB * HW * CC];
__device__ float g_sims[(size_t)BB * SS * TT];
__device__ int   g_idx [(size_t)BB * SS * TT];

// ---------------- LayerNorm: x (B,C,H,W) -> split bf16 (B,HW,C) -------------------
__global__ void ln_kernel(const float* __restrict__ x,
                          const float* __restrict__ lnw,
                          const float* __restrict__ lnb) {
    __shared__ float tile[256][33];
    __shared__ float red_s[8][32], red_ss[8][32];
    __shared__ float s_mean[32], s_inv[32];

    int blk = blockIdx.x;            // 1024 blocks, 512 per batch
    int b   = blk >> 9;
    int n0  = (blk & 511) * 32;
    int tid = threadIdx.x;           // 256
    int tn  = tid & 31;
    int cg  = tid >> 5;              // warp id 0..7

    const float* xb = x + (size_t)b * CC * HW;

#pragma unroll 8
    for (int r = 0; r < 32; r++) {
        int c = r * 8 + cg;
        tile[c][tn] = xb[(size_t)c * HW + n0 + tn];
    }
    __syncthreads();

    float s = 0.f, ss = 0.f;
#pragma unroll 8
    for (int j = 0; j < 32; j++) {
        float v = tile[cg * 32 + j][tn];
        s += v; ss += v * v;
    }
    red_s[cg][tn] = s; red_ss[cg][tn] = ss;
    __syncthreads();
    if (cg == 0) {
        float S = 0.f, SSU = 0.f;
#pragma unroll
        for (int j = 0; j < 8; j++) { S += red_s[j][tn]; SSU += red_ss[j][tn]; }
        float m   = S * (1.0f / 256.0f);
        float var = SSU * (1.0f / 256.0f) - m * m;
        s_mean[tn] = m;
        s_inv[tn]  = rsqrtf(var + LN_EPS);
    }
    __syncthreads();

    float wv = lnw[tid], bv = lnb[tid];
    size_t rb = (size_t)(b * HW + n0) * CC + tid;
#pragma unroll 8
    for (int it = 0; it < 32; it++) {
        float v = tile[tid][it];
        float y = (v - s_mean[it]) * s_inv[it] * wv + bv;
        __nv_bfloat16 hi = __float2bfloat16(y);
        g_xh[rb + (size_t)it * CC] = hi;
        g_xl[rb + (size_t)it * CC] = __float2bfloat16(y - __bfloat162float(hi));
    }
}

// ---------------- split weights into bf16 hi/lo (SCALE folded into wq) -----------
__global__ void wsplit_kernel(const float* __restrict__ Wq,
                              const float* __restrict__ Wk,
                              const float* __restrict__ Wv) {
    int i = blockIdx.x * 256 + threadIdx.x;        // 0 .. 3*65536-1
    int mat = i >> 16, j = i & 65535;
    const float* W = (mat == 0) ? Wq : ((mat == 1) ? Wk : Wv);
    float f = W[j];
    if (mat == 0) f *= SCALE;
    __nv_bfloat16 hi = __float2bfloat16(f);
    g_wh[i] = hi;
    g_wl[i] = __float2bfloat16(f - __bfloat162float(hi));
}

// ---------------- projection GEMM on HMMA (mma.sync, split-bf16 3-product) --------
// Outputs split bf16 q/k/v; mat==2 also writes V transposed into out[b][c][n].
#define STRA 40                         // smem row stride (bf16 units)
#define GT_SMEM (4 * 128 * STRA * 2)    // Ah, Al, Bh, Bl tiles

__global__ void __launch_bounds__(256, 1) gemm_tc_kernel(float* __restrict__ out) {
    extern __shared__ __nv_bfloat16 sm_bf[];
    __nv_bfloat16* Ah = sm_bf;
    __nv_bfloat16* Al = Ah + 128 * STRA;
    __nv_bfloat16* Bh = Al + 128 * STRA;
    __nv_bfloat16* Bl = Bh + 128 * STRA;

    int mat = blockIdx.z;
    __nv_bfloat16* Oh = (mat == 0) ? g_qh : ((mat == 1) ? g_kh : g_vh);
    __nv_bfloat16* Ol = (mat == 0) ? g_ql : ((mat == 1) ? g_kl : g_vl);
    size_t bm = (size_t)blockIdx.x * 128;
    int bn = blockIdx.y * 128;

    int tid = threadIdx.x;
    int wid = tid >> 5, lane = tid & 31;
    int grp = lane >> 2, tig = lane & 3;
    int wm = (wid & 1) * 64, wn = (wid >> 1) * 32;

    const __nv_bfloat16* wh_b = g_wh + (size_t)mat * 65536;
    const __nv_bfloat16* wl_b = g_wl + (size_t)mat * 65536;

    int lr = tid >> 1, lh = tid & 1;
    const uint4* pAh = (const uint4*)(g_xh + (bm + lr) * 256 + lh * 16);
    const uint4* pAl = (const uint4*)(g_xl + (bm + lr) * 256 + lh * 16);
    const uint4* pBh = (const uint4*)(wh_b + (size_t)(bn + lr) * 256 + lh * 16);
    const uint4* pBl = (const uint4*)(wl_b + (size_t)(bn + lr) * 256 + lh * 16);
    int soff = lr * STRA + lh * 16;

    float acc[4][4][4];
#pragma unroll
    for (int mi = 0; mi < 4; mi++)
#pragma unroll
        for (int ni = 0; ni < 4; ni++)
#pragma unroll
            for (int rgi = 0; rgi < 4; rgi++) acc[mi][ni][rgi] = 0.f;

    uint4 rAh[2], rAl[2], rBh[2], rBl[2];
#pragma unroll
    for (int q = 0; q < 2; q++) {
        rAh[q] = pAh[q]; rAl[q] = pAl[q];
        rBh[q] = pBh[q]; rBl[q] = pBl[q];
    }

#pragma unroll 1
    for (int chunk = 0; chunk < 8; chunk++) {
#pragma unroll
        for (int q = 0; q < 2; q++) {
            *(uint4*)(Ah + soff + q * 8) = rAh[q];
            *(uint4*)(Al + soff + q * 8) = rAl[q];
            *(uint4*)(Bh + soff + q * 8) = rBh[q];
            *(uint4*)(Bl + soff + q * 8) = rBl[q];
        }
        __syncthreads();

        int nc = (chunk < 7) ? (chunk + 1) : 7;
        int gofs = nc * 4;
#pragma unroll
        for (int q = 0; q < 2; q++) {
            rAh[q] = pAh[gofs + q]; rAl[q] = pAl[gofs + q];
            rBh[q] = pBh[gofs + q]; rBl[q] = pBl[gofs + q];
        }

#pragma unroll
        for (int ks = 0; ks < 32; ks += 16) {
            uint32_t ah[4][4], al[4][4], bh[4][2], bl[4][2];
            int ca = ks + tig * 2;
#pragma unroll
            for (int mi = 0; mi < 4; mi++) {
                int r0 = wm + mi * 16 + grp;
                ah[mi][0] = *(const uint32_t*)(Ah + r0 * STRA + ca);
                ah[mi][1] = *(const uint32_t*)(Ah + (r0 + 8) * STRA + ca);
                ah[mi][2] = *(const uint32_t*)(Ah + r0 * STRA + ca + 8);
                ah[mi][3] = *(const uint32_t*)(Ah + (r0 + 8) * STRA + ca + 8);
                al[mi][0] = *(const uint32_t*)(Al + r0 * STRA + ca);
                al[mi][1] = *(const uint32_t*)(Al + (r0 + 8) * STRA + ca);
                al[mi][2] = *(const uint32_t*)(Al + r0 * STRA + ca + 8);
                al[mi][3] = *(const uint32_t*)(Al + (r0 + 8) * STRA + ca + 8);
            }
#pragma unroll
            for (int ni = 0; ni < 4; ni++) {
                int n0 = wn + ni * 8 + grp;
                bh[ni][0] = *(const uint32_t*)(Bh + n0 * STRA + ca);
                bh[ni][1] = *(const uint32_t*)(Bh + n0 * STRA + ca + 8);
                bl[ni][0] = *(const uint32_t*)(Bl + n0 * STRA + ca);
                bl[ni][1] = *(const uint32_t*)(Bl + n0 * STRA + ca + 8);
            }
#pragma unroll
            for (int mi = 0; mi < 4; mi++)
#pragma unroll
                for (int ni = 0; ni < 4; ni++) {
                    float* c = acc[mi][ni];
                    MMA_BF16(c[0], c[1], c[2], c[3],
                             ah[mi][0], ah[mi][1], ah[mi][2], ah[mi][3],
                             bh[ni][0], bh[ni][1]);
                    MMA_BF16(c[0], c[1], c[2], c[3],
                             ah[mi][0], ah[mi][1], ah[mi][2], ah[mi][3],
                             bl[ni][0], bl[ni][1]);
                    MMA_BF16(c[0], c[1], c[2], c[3],
                             al[mi][0], al[mi][1], al[mi][2], al[mi][3],
                             bh[ni][0], bh[ni][1]);
                }
        }
        __syncthreads();
    }

    // epilogue: split-bf16 store (hi + residual lo)
#pragma unroll
    for (int mi = 0; mi < 4; mi++) {
#pragma unroll
        for (int ni = 0; ni < 4; ni++) {
            float* c = acc[mi][ni];
            size_t row0 = bm + wm + mi * 16 + grp;
            size_t row1 = row0 + 8;
            int col = bn + wn + ni * 8 + tig * 2;
            __nv_bfloat16 h0 = __float2bfloat16(c[0]);
            __nv_bfloat16 h1 = __float2bfloat16(c[1]);
            __nv_bfloat16 h2 = __float2bfloat16(c[2]);
            __nv_bfloat16 h3 = __float2bfloat16(c[3]);
            *(uint32_t*)&Oh[row0 * 256 + col] = pk2(h0, h1);
            *(uint32_t*)&Oh[row1 * 256 + col] = pk2(h2, h3);
            *(uint32_t*)&Ol[row0 * 256 + col] =
                pk2(__float2bfloat16(c[0] - __bfloat162float(h0)),
                    __float2bfloat16(c[1] - __bfloat162float(h1)));
            *(uint32_t*)&Ol[row1 * 256 + col] =
                pk2(__float2bfloat16(c[2] - __bfloat162float(h2)),
                    __float2bfloat16(c[3] - __bfloat162float(h3)));
            if (mat == 2) {
                int b0 = (int)(row0 >> 14), n0 = (int)(row0 & 16383);
                int b1 = (int)(row1 >> 14), n1 = (int)(row1 & 16383);
                out[((size_t)b0 * CC + col) * HW + n0]     = c[0];
                out[((size_t)b0 * CC + col + 1) * HW + n0] = c[1];
                out[((size_t)b1 * CC + col) * HW + n1]     = c[2];
                out[((size_t)b1 * CC + col + 1) * HW + n1] = c[3];
            }
        }
    }
}

// ---------------- top-k: per (b,s) row of 16384, select top-128 (radix select) ----
// 1024 threads, 4-way replicated histogram, parallel suffix-scan bin selection.
#define TK_N 16384
#define TK_THR 1024
#define TOPK_SMEM ((TK_N + 1024 + 256) * 4)
__global__ void __launch_bounds__(TK_THR) topk_kernel(const float* __restrict__ aff) {
    extern __shared__ unsigned int shm[];
    unsigned int* keys  = shm;               // 16384
    unsigned int* hist  = shm + TK_N;        // 4 copies x 256
    unsigned int* sscan = hist + 1024;       // 256
    __shared__ unsigned int s_prefix, s_rem, s_cntgt, s_cnteq, s_sel, s_gt;
    __shared__ int eq_idx[128];

    int row = blockIdx.x;
    const float* ap = aff + (size_t)row * TK_N;
    int tid = threadIdx.x;
    int hcp = (tid >> 5) & 3;                // histogram copy = warp % 4

    for (int n = tid; n < TK_N; n += TK_THR) {
        unsigned int u = __float_as_uint(ap[n]);
        keys[n] = (u & 0x80000000u) ? ~u : (u | 0x80000000u);
    }
    if (tid == 0) { s_prefix = 0u; s_rem = 128u; s_cntgt = 0u; s_cnteq = 0u; }
    __syncthreads();

    for (int sh = 24; sh >= 0; sh -= 8) {
        for (int i = tid; i < 1024; i += TK_THR) hist[i] = 0u;
        __syncthreads();
        unsigned int pref = s_prefix, rem = s_rem;
        unsigned int mask = (sh == 24) ? 0u : (0xFFFFFFFFu << (sh + 8));
#pragma unroll 4
        for (int n = tid; n < TK_N; n += TK_THR) {
            unsigned int k = keys[n];
            if (((k ^ pref) & mask) == 0u)
                atomicAdd(&hist[hcp * 256 + ((k >> sh) & 0xFF)], 1u);
        }
        __syncthreads();
        if (tid < 256)
            sscan[tid] = hist[tid] + hist[256 + tid] + hist[512 + tid] + hist[768 + tid];
        __syncthreads();
        // suffix sum: sscan[b] = count of keys with byte >= b (within prefix)
#pragma unroll
        for (int off = 1; off < 256; off <<= 1) {
            unsigned int v = 0u, a = 0u;
            if (tid < 256) { v = sscan[tid]; if (tid + off < 256) a = sscan[tid + off]; }
            __syncthreads();
            if (tid < 256) sscan[tid] = v + a;
            __syncthreads();
        }
        if (tid < 256) {
            unsigned int ge = sscan[tid];
            unsigned int gt = (tid < 255) ? sscan[tid + 1] : 0u;
            if (ge >= rem && gt < rem) { s_sel = (unsigned int)tid; s_gt = gt; }
        }
        __syncthreads();
        if (tid == 0) {
            s_prefix = pref | (s_sel << sh);
            s_rem = rem - s_gt;
        }
        __syncthreads();
    }

    unsigned int thr = s_prefix;
    int take_eq = (int)s_rem;
    int n_gt = 128 - take_eq;

    for (int n = tid; n < TK_N; n += TK_THR) {
        unsigned int k = keys[n];
        if (k > thr) {
            int p = (int)atomicAdd(&s_cntgt, 1u);
            g_idx[(size_t)row * 128 + p]  = n;
            g_sims[(size_t)row * 128 + p] = ap[n];
        } else if (k == thr) {
            int e = (int)atomicAdd(&s_cnteq, 1u);
            if (e < 128) eq_idx[e] = n;
        }
    }
    __syncthreads();
    if (tid == 0) {
        int ne = (int)s_cnteq; if (ne > 128) ne = 128;
        // sort ascending so ties break toward lowest index (matches lax.top_k)
        for (int i = 1; i < ne; i++) {
            int v = eq_idx[i]; int j = i - 1;
            while (j >= 0 && eq_idx[j] > v) { eq_idx[j + 1] = eq_idx[j]; j--; }
            eq_idx[j + 1] = v;
        }
        for (int i = 0; i < take_eq; i++) {
            int src = (i < ne) ? i : (ne - 1);
            int n = eq_idx[src];
            g_idx[(size_t)row * 128 + n_gt + i]  = n;
            g_sims[(size_t)row * 128 + n_gt + i] = ap[n];
        }
    }
}

// ---------------- attention per (head, s, b) — HMMA split-bf16 --------------------
// smem bf16: qh/ql/kh/kl [128][40], vh/vl transposed [32][136]; + sims/idx
#define QSTR 40
#define VSTR 136
#define SM_QH 0
#define SM_QL (SM_QH + 128 * QSTR)
#define SM_KH (SM_QL + 128 * QSTR)
#define SM_KL (SM_KH + 128 * QSTR)
#define SM_VH (SM_KL + 128 * QSTR)
#define SM_VL (SM_VH + 32 * VSTR)
#define SM_BF_END (SM_VL + 32 * VSTR)
#define ATTN_SMEM (SM_BF_END * 2 + 128 * 8)

__global__ void __launch_bounds__(256) attn_kernel(float* __restrict__ res) {
    extern __shared__ __nv_bfloat16 abf[];
    __nv_bfloat16* qh = abf + SM_QH;
    __nv_bfloat16* ql = abf + SM_QL;
    __nv_bfloat16* kh = abf + SM_KH;
    __nv_bfloat16* kl = abf + SM_KL;
    __nv_bfloat16* vh = abf + SM_VH;   // [c][u]
    __nv_bfloat16* vl = abf + SM_VL;
    float* sims_s = (float*)(abf + SM_BF_END);
    int*   idx_s  = (int*)(sims_s + 128);

    int h = blockIdx.x, s = blockIdx.y, b = blockIdx.z;
    int tid = threadIdx.x;              // 256
    int wid = tid >> 5, lane = tid & 31;
    int grp = lane >> 2, tig = lane & 3;
    int wm = wid * 16;
    int base = ((b << 8) + s) << 7;

    if (tid < 128) {
        idx_s[tid]  = g_idx[base + tid];
        sims_s[tid] = g_sims[base + tid];
    }
    __syncthreads();

    int coff = h * DH;
    // gather: pure copies (projections already split bf16; SCALE in wq)
    for (int i = tid; i < 1024; i += 256) {
        int u = i >> 3, c = (i & 7) * 4;
        size_t off = ((size_t)(b * HW + idx_s[u])) * 256 + coff + c;
        uint2 vqh = *(const uint2*)&g_qh[off];
        uint2 vql = *(const uint2*)&g_ql[off];
        uint2 vkh = *(const uint2*)&g_kh[off];
        uint2 vkl = *(const uint2*)&g_kl[off];
        uint2 vvh = *(const uint2*)&g_vh[off];
        uint2 vvl = *(const uint2*)&g_vl[off];
        *(uint2*)&qh[u * QSTR + c] = vqh;
        *(uint2*)&ql[u * QSTR + c] = vql;
        *(uint2*)&kh[u * QSTR + c] = vkh;
        *(uint2*)&kl[u * QSTR + c] = vkl;
        __nv_bfloat16 th[4], tl[4];
        *(uint2*)th = vvh; *(uint2*)tl = vvl;
#pragma unroll
        for (int j = 0; j < 4; j++) {
            vh[(c + j) * VSTR + u] = th[j];
            vl[(c + j) * VSTR + u] = tl[j];
        }
    }
    __syncthreads();

    // GEMM1: S[wm+.., 128] = Q·K^T (3-product split), acc[16 n-tiles][4]
    float acc[16][4];
#pragma unroll
    for (int nt = 0; nt < 16; nt++)
#pragma unroll
        for (int rgi = 0; rgi < 4; rgi++) acc[nt][rgi] = 0.f;

#pragma unroll
    for (int ks = 0; ks < 2; ks++) {
        int ca = ks * 16 + tig * 2;
        uint32_t ah0 = *(const uint32_t*)&qh[(wm + grp) * QSTR + ca];
        uint32_t ah1 = *(const uint32_t*)&qh[(wm + grp + 8) * QSTR + ca];
        uint32_t ah2 = *(const uint32_t*)&qh[(wm + grp) * QSTR + ca + 8];
        uint32_t ah3 = *(const uint32_t*)&qh[(wm + grp + 8) * QSTR + ca + 8];
        uint32_t al0 = *(const uint32_t*)&ql[(wm + grp) * QSTR + ca];
        uint32_t al1 = *(const uint32_t*)&ql[(wm + grp + 8) * QSTR + ca];
        uint32_t al2 = *(const uint32_t*)&ql[(wm + grp) * QSTR + ca + 8];
        uint32_t al3 = *(const uint32_t*)&ql[(wm + grp + 8) * QSTR + ca + 8];
#pragma unroll
        for (int nt = 0; nt < 16; nt++) {
            int ro = (nt * 8 + grp) * QSTR + ca;
            uint32_t bh0 = *(const uint32_t*)&kh[ro];
            uint32_t bh1 = *(const uint32_t*)&kh[ro + 8];
            uint32_t bl0 = *(const uint32_t*)&kl[ro];
            uint32_t bl1 = *(const uint32_t*)&kl[ro + 8];
            float* c = acc[nt];
            MMA_BF16(c[0], c[1], c[2], c[3], ah0, ah1, ah2, ah3, bh0, bh1);
            MMA_BF16(c[0], c[1], c[2], c[3], ah0, ah1, ah2, ah3, bl0, bl1);
            MMA_BF16(c[0], c[1], c[2], c[3], al0, al1, al2, al3, bh0, bh1);
        }
    }

    // softmax in registers: rows wm+grp (c0,c1) and wm+grp+8 (c2,c3)
    float mx0 = -3.4e38f, mx1 = -3.4e38f;
#pragma unroll
    for (int nt = 0; nt < 16; nt++) {
        mx0 = fmaxf(mx0, fmaxf(acc[nt][0], acc[nt][1]));
        mx1 = fmaxf(mx1, fmaxf(acc[nt][2], acc[nt][3]));
    }
#pragma unroll
    for (int m = 1; m <= 2; m <<= 1) {
        mx0 = fmaxf(mx0, __shfl_xor_sync(0xffffffffu, mx0, m));
        mx1 = fmaxf(mx1, __shfl_xor_sync(0xffffffffu, mx1, m));
    }
    float sum0 = 0.f, sum1 = 0.f;
#pragma unroll
    for (int nt = 0; nt < 16; nt++) {
        acc[nt][0] = __expf(acc[nt][0] - mx0);
        acc[nt][1] = __expf(acc[nt][1] - mx0);
        acc[nt][2] = __expf(acc[nt][2] - mx1);
        acc[nt][3] = __expf(acc[nt][3] - mx1);
        sum0 += acc[nt][0] + acc[nt][1];
        sum1 += acc[nt][2] + acc[nt][3];
    }
#pragma unroll
    for (int m = 1; m <= 2; m <<= 1) {
        sum0 += __shfl_xor_sync(0xffffffffu, sum0, m);
        sum1 += __shfl_xor_sync(0xffffffffu, sum1, m);
    }

    // GEMM2: O = (P .* sims[u]) · V, P from acc regs (sims folded per-column)
    float ot[4][4];
#pragma unroll
    for (int nt = 0; nt < 4; nt++)
#pragma unroll
        for (int rgi = 0; rgi < 4; rgi++) ot[nt][rgi] = 0.f;

#pragma unroll
    for (int ks = 0; ks < 8; ks++) {
        float* t0 = acc[2 * ks];
        float* t1 = acc[2 * ks + 1];
        float w00 = sims_s[ks * 16 + tig * 2];
        float w01 = sims_s[ks * 16 + tig * 2 + 1];
        float w10 = sims_s[ks * 16 + 8 + tig * 2];
        float w11 = sims_s[ks * 16 + 8 + tig * 2 + 1];
        float p00 = t0[0] * w00, p01 = t0[1] * w01;
        float p02 = t0[2] * w00, p03 = t0[3] * w01;
        float p10 = t1[0] * w10, p11 = t1[1] * w11;
        float p12 = t1[2] * w10, p13 = t1[3] * w11;
        __nv_bfloat16 h00 = __float2bfloat16(p00), h01 = __float2bfloat16(p01);
        __nv_bfloat16 h02 = __float2bfloat16(p02), h03 = __float2bfloat16(p03);
        __nv_bfloat16 h10 = __float2bfloat16(p10), h11 = __float2bfloat16(p11);
        __nv_bfloat16 h12 = __float2bfloat16(p12), h13 = __float2bfloat16(p13);
        uint32_t ah0 = pk2(h00, h01), ah1 = pk2(h02, h03);
        uint32_t ah2 = pk2(h10, h11), ah3 = pk2(h12, h13);
        uint32_t al0 = pk2(__float2bfloat16(p00 - __bfloat162float(h00)),
                           __float2bfloat16(p01 - __bfloat162float(h01)));
        uint32_t al1 = pk2(__float2bfloat16(p02 - __bfloat162float(h02)),
                           __float2bfloat16(p03 - __bfloat162float(h03)));
        uint32_t al2 = pk2(__float2bfloat16(p10 - __bfloat162float(h10)),
                           __float2bfloat16(p11 - __bfloat162float(h11)));
        uint32_t al3 = pk2(__float2bfloat16(p12 - __bfloat162float(h12)),
                           __float2bfloat16(p13 - __bfloat162float(h13)));
        int ub = ks * 16 + tig * 2;
#pragma unroll
        for (int nt = 0; nt < 4; nt++) {
            int bo = (nt * 8 + grp) * VSTR + ub;
            uint32_t bh0 = *(const uint32_t*)&vh[bo];
            uint32_t bh1 = *(const uint32_t*)&vh[bo + 8];
            uint32_t bl0 = *(const uint32_t*)&vl[bo];
            uint32_t bl1 = *(const uint32_t*)&vl[bo + 8];
            float* c = ot[nt];
            MMA_BF16(c[0], c[1], c[2], c[3], ah0, ah1, ah2, ah3, bh0, bh1);
            MMA_BF16(c[0], c[1], c[2], c[3], ah0, ah1, ah2, ah3, bl0, bl1);
            MMA_BF16(c[0], c[1], c[2], c[3], al0, al1, al2, al3, bh0, bh1);
        }
    }

    // scatter with row scale sims/sum
    {
        int r0 = wm + grp, r1 = wm + grp + 8;
        float rs0 = sims_s[r0] / sum0;
        float rs1 = sims_s[r1] / sum1;
        int n0 = idx_s[r0], n1 = idx_s[r1];
        float* rp = res + ((size_t)b * CC + coff) * HW;
#pragma unroll
        for (int nt = 0; nt < 4; nt++) {
            int c0 = nt * 8 + tig * 2;
            atomicAdd(rp + (size_t)c0 * HW + n0,       ot[nt][0] * rs0);
            atomicAdd(rp + (size_t)(c0 + 1) * HW + n0, ot[nt][1] * rs0);
            atomicAdd(rp + (size_t)c0 * HW + n1,       ot[nt][2] * rs1);
            atomicAdd(rp + (size_t)(c0 + 1) * HW + n1, ot[nt][3] * rs1);
        }
    }
}

// ---------------- launch ----------------
extern "C" void kernel_launch(void* const* d_in, const int* in_sizes, int n_in,
                              void* d_out, int out_size) {
    const float* x   = (const float*)d_in[0];
    const float* aff = (const float*)d_in[1];
    const float* lnw = (const float*)d_in[2];
    const float* lnb = (const float*)d_in[3];
    const float* wq  = (const float*)d_in[4];
    const float* wk  = (const float*)d_in[5];
    const float* wv  = (const float*)d_in[6];
    float* out = (float*)d_out;

    cudaFuncSetAttribute(topk_kernel, cudaFuncAttributeMaxDynamicSharedMemorySize, TOPK_SMEM);
    cudaFuncSetAttribute(attn_kernel, cudaFuncAttributeMaxDynamicSharedMemorySize, ATTN_SMEM);
    cudaFuncSetAttribute(gemm_tc_kernel, cudaFuncAttributeMaxDynamicSharedMemorySize, GT_SMEM);

    ln_kernel<<<1024, 256>>>(x, lnw, lnb);
    wsplit_kernel<<<768, 256>>>(wq, wk, wv);
    gemm_tc_kernel<<<dim3(256, 2, 3), 256, GT_SMEM>>>(out);
    topk_kernel<<<BB * SS, TK_THR, TOPK_SMEM>>>(aff);
    attn_kernel<<<dim3(NH, SS, BB), 256, ATTN_SMEM>>>(out);
}

// round 13
// speedup vs baseline: 1.0653x; 1.0653x over previous
#include <cuda_runtime.h>
#include <cuda_bf16.h>
#include <cstdint>

// Problem constants
#define BB 2
#define CC 256
#define HW 16384
#define SS 256
#define TT 128
#define NH 8
#define DH 32
#define SCALE 0.17677669529663689f   // 32^-0.5
#define LN_EPS 1e-5f

typedef unsigned long long u64;

// warp-level bf16 MMA, m16n8k16, fp32 accumulate (baseline PTX)
#define MMA_BF16(c0,c1,c2,c3, a0,a1,a2,a3, b0,b1) \
    asm("mma.sync.aligned.m16n8k16.row.col.f32.bf16.bf16.f32 " \
        "{%0,%1,%2,%3}, {%4,%5,%6,%7}, {%8,%9}, {%0,%1,%2,%3};" \
        : "+f"(c0), "+f"(c1), "+f"(c2), "+f"(c3) \
        : "r"(a0), "r"(a1), "r"(a2), "r"(a3), "r"(b0), "r"(b1))

__device__ __forceinline__ uint32_t pk2(__nv_bfloat16 a, __nv_bfloat16 b) {
    unsigned short ua = *(unsigned short*)&a, ub = *(unsigned short*)&b;
    return (uint32_t)ua | ((uint32_t)ub << 16);
}

// ---------------- scratch (device globals; no allocation allowed) ----------------
__device__ __nv_bfloat16 g_xh[(size_t)BB * HW * CC];  // LN output hi bf16, [m][c]
__device__ __nv_bfloat16 g_xl[(size_t)BB * HW * CC];  // LN output lo bf16
__device__ __nv_bfloat16 g_wh[3 * CC * CC];           // W hi bf16 (wq pre-scaled)
__device__ __nv_bfloat16 g_wl[3 * CC * CC];
// projections, split bf16 interleaved: unit p = channel pair, layout
// [m][p] -> 4 bf16: {hi(2p), hi(2p+1), lo(2p), lo(2p+1)}  (8 bytes per unit)
__device__ __nv_bfloat16 g_qi[(size_t)BB * HW * CC * 2];
__device__ __nv_bfloat16 g_ki[(size_t)BB * HW * CC * 2];
__device__ __nv_bfloat16 g_vi[(size_t)BB * HW * CC * 2];
__device__ float g_sims[(size_t)BB * SS * TT];
__device__ int   g_idx [(size_t)BB * SS * TT];

// ---------------- LayerNorm: x (B,C,H,W) -> split bf16 (B,HW,C) -------------------
__global__ void ln_kernel(const float* __restrict__ x,
                          const float* __restrict__ lnw,
                          const float* __restrict__ lnb) {
    __shared__ float tile[256][33];
    __shared__ float red_s[8][32], red_ss[8][32];
    __shared__ float s_mean[32], s_inv[32];

    int blk = blockIdx.x;            // 1024 blocks, 512 per batch
    int b   = blk >> 9;
    int n0  = (blk & 511) * 32;
    int tid = threadIdx.x;           // 256
    int tn  = tid & 31;
    int cg  = tid >> 5;              // warp id 0..7

    const float* xb = x + (size_t)b * CC * HW;

#pragma unroll 8
    for (int r = 0; r < 32; r++) {
        int c = r * 8 + cg;
        tile[c][tn] = xb[(size_t)c * HW + n0 + tn];
    }
    __syncthreads();

    float s = 0.f, ss = 0.f;
#pragma unroll 8
    for (int j = 0; j < 32; j++) {
        float v = tile[cg * 32 + j][tn];
        s += v; ss += v * v;
    }
    red_s[cg][tn] = s; red_ss[cg][tn] = ss;
    __syncthreads();
    if (cg == 0) {
        float S = 0.f, SSU = 0.f;
#pragma unroll
        for (int j = 0; j < 8; j++) { S += red_s[j][tn]; SSU += red_ss[j][tn]; }
        float m   = S * (1.0f / 256.0f);
        float var = SSU * (1.0f / 256.0f) - m * m;
        s_mean[tn] = m;
        s_inv[tn]  = rsqrtf(var + LN_EPS);
    }
    __syncthreads();

    float wv = lnw[tid], bv = lnb[tid];
    size_t rb = (size_t)(b * HW + n0) * CC + tid;
#pragma unroll 8
    for (int it = 0; it < 32; it++) {
        float v = tile[tid][it];
        float y = (v - s_mean[it]) * s_inv[it] * wv + bv;
        __nv_bfloat16 hi = __float2bfloat16(y);
        g_xh[rb + (size_t)it * CC] = hi;
        g_xl[rb + (size_t)it * CC] = __float2bfloat16(y - __bfloat162float(hi));
    }
}

// ---------------- split weights into bf16 hi/lo (SCALE folded into wq) -----------
__global__ void wsplit_kernel(const float* __restrict__ Wq,
                              const float* __restrict__ Wk,
                              const float* __restrict__ Wv) {
    int i = blockIdx.x * 256 + threadIdx.x;        // 0 .. 3*65536-1
    int mat = i >> 16, j = i & 65535;
    const float* W = (mat == 0) ? Wq : ((mat == 1) ? Wk : Wv);
    float f = W[j];
    if (mat == 0) f *= SCALE;
    __nv_bfloat16 hi = __float2bfloat16(f);
    g_wh[i] = hi;
    g_wl[i] = __float2bfloat16(f - __bfloat162float(hi));
}

// ---------------- projection GEMM on HMMA (mma.sync, split-bf16 3-product) --------
// Outputs interleaved split bf16 q/k/v; mat==2 also writes V into out[b][c][n].
#define STRA 40                         // smem row stride (bf16 units)
#define GT_SMEM (4 * 128 * STRA * 2)    // Ah, Al, Bh, Bl tiles

__global__ void __launch_bounds__(256, 1) gemm_tc_kernel(float* __restrict__ out) {
    extern __shared__ __nv_bfloat16 sm_bf[];
    __nv_bfloat16* Ah = sm_bf;
    __nv_bfloat16* Al = Ah + 128 * STRA;
    __nv_bfloat16* Bh = Al + 128 * STRA;
    __nv_bfloat16* Bl = Bh + 128 * STRA;

    int mat = blockIdx.z;
    __nv_bfloat16* Oi = (mat == 0) ? g_qi : ((mat == 1) ? g_ki : g_vi);
    size_t bm = (size_t)blockIdx.x * 128;
    int bn = blockIdx.y * 128;

    int tid = threadIdx.x;
    int wid = tid >> 5, lane = tid & 31;
    int grp = lane >> 2, tig = lane & 3;
    int wm = (wid & 1) * 64, wn = (wid >> 1) * 32;

    const __nv_bfloat16* wh_b = g_wh + (size_t)mat * 65536;
    const __nv_bfloat16* wl_b = g_wl + (size_t)mat * 65536;

    int lr = tid >> 1, lh = tid & 1;
    const uint4* pAh = (const uint4*)(g_xh + (bm + lr) * 256 + lh * 16);
    const uint4* pAl = (const uint4*)(g_xl + (bm + lr) * 256 + lh * 16);
    const uint4* pBh = (const uint4*)(wh_b + (size_t)(bn + lr) * 256 + lh * 16);
    const uint4* pBl = (const uint4*)(wl_b + (size_t)(bn + lr) * 256 + lh * 16);
    int soff = lr * STRA + lh * 16;

    float acc[4][4][4];
#pragma unroll
    for (int mi = 0; mi < 4; mi++)
#pragma unroll
        for (int ni = 0; ni < 4; ni++)
#pragma unroll
            for (int rgi = 0; rgi < 4; rgi++) acc[mi][ni][rgi] = 0.f;

    uint4 rAh[2], rAl[2], rBh[2], rBl[2];
#pragma unroll
    for (int q = 0; q < 2; q++) {
        rAh[q] = pAh[q]; rAl[q] = pAl[q];
        rBh[q] = pBh[q]; rBl[q] = pBl[q];
    }

#pragma unroll 1
    for (int chunk = 0; chunk < 8; chunk++) {
#pragma unroll
        for (int q = 0; q < 2; q++) {
            *(uint4*)(Ah + soff + q * 8) = rAh[q];
            *(uint4*)(Al + soff + q * 8) = rAl[q];
            *(uint4*)(Bh + soff + q * 8) = rBh[q];
            *(uint4*)(Bl + soff + q * 8) = rBl[q];
        }
        __syncthreads();

        int nc = (chunk < 7) ? (chunk + 1) : 7;
        int gofs = nc * 4;
#pragma unroll
        for (int q = 0; q < 2; q++) {
            rAh[q] = pAh[gofs + q]; rAl[q] = pAl[gofs + q];
            rBh[q] = pBh[gofs + q]; rBl[q] = pBl[gofs + q];
        }

#pragma unroll
        for (int ks = 0; ks < 32; ks += 16) {
            uint32_t ah[4][4], al[4][4], bh[4][2], bl[4][2];
            int ca = ks + tig * 2;
#pragma unroll
            for (int mi = 0; mi < 4; mi++) {
                int r0 = wm + mi * 16 + grp;
                ah[mi][0] = *(const uint32_t*)(Ah + r0 * STRA + ca);
                ah[mi][1] = *(const uint32_t*)(Ah + (r0 + 8) * STRA + ca);
                ah[mi][2] = *(const uint32_t*)(Ah + r0 * STRA + ca + 8);
                ah[mi][3] = *(const uint32_t*)(Ah + (r0 + 8) * STRA + ca + 8);
                al[mi][0] = *(const uint32_t*)(Al + r0 * STRA + ca);
                al[mi][1] = *(const uint32_t*)(Al + (r0 + 8) * STRA + ca);
                al[mi][2] = *(const uint32_t*)(Al + r0 * STRA + ca + 8);
                al[mi][3] = *(const uint32_t*)(Al + (r0 + 8) * STRA + ca + 8);
            }
#pragma unroll
            for (int ni = 0; ni < 4; ni++) {
                int n0 = wn + ni * 8 + grp;
                bh[ni][0] = *(const uint32_t*)(Bh + n0 * STRA + ca);
                bh[ni][1] = *(const uint32_t*)(Bh + n0 * STRA + ca + 8);
                bl[ni][0] = *(const uint32_t*)(Bl + n0 * STRA + ca);
                bl[ni][1] = *(const uint32_t*)(Bl + n0 * STRA + ca + 8);
            }
#pragma unroll
            for (int mi = 0; mi < 4; mi++)
#pragma unroll
                for (int ni = 0; ni < 4; ni++) {
                    float* c = acc[mi][ni];
                    MMA_BF16(c[0], c[1], c[2], c[3],
                             ah[mi][0], ah[mi][1], ah[mi][2], ah[mi][3],
                             bh[ni][0], bh[ni][1]);
                    MMA_BF16(c[0], c[1], c[2], c[3],
                             ah[mi][0], ah[mi][1], ah[mi][2], ah[mi][3],
                             bl[ni][0], bl[ni][1]);
                    MMA_BF16(c[0], c[1], c[2], c[3],
                             al[mi][0], al[mi][1], al[mi][2], al[mi][3],
                             bh[ni][0], bh[ni][1]);
                }
        }
        __syncthreads();
    }

    // epilogue: interleaved split store — one uint2 per (row, channel-pair)
#pragma unroll
    for (int mi = 0; mi < 4; mi++) {
#pragma unroll
        for (int ni = 0; ni < 4; ni++) {
            float* c = acc[mi][ni];
            size_t row0 = bm + wm + mi * 16 + grp;
            size_t row1 = row0 + 8;
            int col = bn + wn + ni * 8 + tig * 2;   // even channel pair base
            __nv_bfloat16 h0 = __float2bfloat16(c[0]);
            __nv_bfloat16 h1 = __float2bfloat16(c[1]);
            __nv_bfloat16 h2 = __float2bfloat16(c[2]);
            __nv_bfloat16 h3 = __float2bfloat16(c[3]);
            uint2 v0, v1;
            v0.x = pk2(h0, h1);
            v0.y = pk2(__float2bfloat16(c[0] - __bfloat162float(h0)),
                       __float2bfloat16(c[1] - __bfloat162float(h1)));
            v1.x = pk2(h2, h3);
            v1.y = pk2(__float2bfloat16(c[2] - __bfloat162float(h2)),
                       __float2bfloat16(c[3] - __bfloat162float(h3)));
            *(uint2*)&Oi[(row0 * 128 + (col >> 1)) * 4] = v0;
            *(uint2*)&Oi[(row1 * 128 + (col >> 1)) * 4] = v1;
            if (mat == 2) {
                int b0 = (int)(row0 >> 14), n0 = (int)(row0 & 16383);
                int b1 = (int)(row1 >> 14), n1 = (int)(row1 & 16383);
                out[((size_t)b0 * CC + col) * HW + n0]     = c[0];
                out[((size_t)b0 * CC + col + 1) * HW + n0] = c[1];
                out[((size_t)b1 * CC + col) * HW + n1]     = c[2];
                out[((size_t)b1 * CC + col + 1) * HW + n1] = c[3];
            }
        }
    }
}

// ---------------- top-k: per (b,s) row of 16384, select top-128 (radix select) ----
// 512 threads, 4-way replicated histogram, parallel suffix-scan bin selection.
#define TK_N 16384
#define TK_THR 512
#define TOPK_SMEM ((TK_N + 1024 + 256) * 4)
__global__ void __launch_bounds__(TK_THR) topk_kernel(const float* __restrict__ aff) {
    extern __shared__ unsigned int shm[];
    unsigned int* keys  = shm;               // 16384
    unsigned int* hist  = shm + TK_N;        // 4 copies x 256
    unsigned int* sscan = hist + 1024;       // 256
    __shared__ unsigned int s_prefix, s_rem, s_cntgt, s_cnteq, s_sel, s_gt;
    __shared__ int eq_idx[128];

    int row = blockIdx.x;
    const float* ap = aff + (size_t)row * TK_N;
    int tid = threadIdx.x;
    int hcp = (tid >> 5) & 3;                // histogram copy = warp % 4

    for (int n = tid; n < TK_N; n += TK_THR) {
        unsigned int u = __float_as_uint(ap[n]);
        keys[n] = (u & 0x80000000u) ? ~u : (u | 0x80000000u);
    }
    if (tid == 0) { s_prefix = 0u; s_rem = 128u; s_cntgt = 0u; s_cnteq = 0u; }
    __syncthreads();

    for (int sh = 24; sh >= 0; sh -= 8) {
        for (int i = tid; i < 1024; i += TK_THR) hist[i] = 0u;
        __syncthreads();
        unsigned int pref = s_prefix, rem = s_rem;
        unsigned int mask = (sh == 24) ? 0u : (0xFFFFFFFFu << (sh + 8));
#pragma unroll 8
        for (int n = tid; n < TK_N; n += TK_THR) {
            unsigned int k = keys[n];
            if (((k ^ pref) & mask) == 0u)
                atomicAdd(&hist[hcp * 256 + ((k >> sh) & 0xFF)], 1u);
        }
        __syncthreads();
        if (tid < 256)
            sscan[tid] = hist[tid] + hist[256 + tid] + hist[512 + tid] + hist[768 + tid];
        __syncthreads();
        // suffix sum: sscan[b] = count of keys with byte >= b (within prefix)
#pragma unroll
        for (int off = 1; off < 256; off <<= 1) {
            unsigned int v = 0u, a = 0u;
            if (tid < 256) { v = sscan[tid]; if (tid + off < 256) a = sscan[tid + off]; }
            __syncthreads();
            if (tid < 256) sscan[tid] = v + a;
            __syncthreads();
        }
        if (tid < 256) {
            unsigned int ge = sscan[tid];
            unsigned int gt = (tid < 255) ? sscan[tid + 1] : 0u;
            if (ge >= rem && gt < rem) { s_sel = (unsigned int)tid; s_gt = gt; }
        }
        __syncthreads();
        if (tid == 0) {
            s_prefix = pref | (s_sel << sh);
            s_rem = rem - s_gt;
        }
        __syncthreads();
    }

    unsigned int thr = s_prefix;
    int take_eq = (int)s_rem;
    int n_gt = 128 - take_eq;

    for (int n = tid; n < TK_N; n += TK_THR) {
        unsigned int k = keys[n];
        if (k > thr) {
            int p = (int)atomicAdd(&s_cntgt, 1u);
            g_idx[(size_t)row * 128 + p]  = n;
            g_sims[(size_t)row * 128 + p] = ap[n];
        } else if (k == thr) {
            int e = (int)atomicAdd(&s_cnteq, 1u);
            if (e < 128) eq_idx[e] = n;
        }
    }
    __syncthreads();
    if (tid == 0) {
        int ne = (int)s_cnteq; if (ne > 128) ne = 128;
        // sort ascending so ties break toward lowest index (matches lax.top_k)
        for (int i = 1; i < ne; i++) {
            int v = eq_idx[i]; int j = i - 1;
            while (j >= 0 && eq_idx[j] > v) { eq_idx[j + 1] = eq_idx[j]; j--; }
            eq_idx[j + 1] = v;
        }
        for (int i = 0; i < take_eq; i++) {
            int src = (i < ne) ? i : (ne - 1);
            int n = eq_idx[src];
            g_idx[(size_t)row * 128 + n_gt + i]  = n;
            g_sims[(size_t)row * 128 + n_gt + i] = ap[n];
        }
    }
}

// ---------------- attention per (head, s, b) — HMMA split-bf16 --------------------
// smem bf16: qh/ql/kh/kl [128][40], vh/vl transposed [32][136]; + sims/idx
#define QSTR 40
#define VSTR 136
#define SM_QH 0
#define SM_QL (SM_QH + 128 * QSTR)
#define SM_KH (SM_QL + 128 * QSTR)
#define SM_KL (SM_KH + 128 * QSTR)
#define SM_VH (SM_KL + 128 * QSTR)
#define SM_VL (SM_VH + 32 * VSTR)
#define SM_BF_END (SM_VL + 32 * VSTR)
#define ATTN_SMEM (SM_BF_END * 2 + 128 * 8)

__global__ void __launch_bounds__(256) attn_kernel(float* __restrict__ res) {
    extern __shared__ __nv_bfloat16 abf[];
    __nv_bfloat16* qh = abf + SM_QH;
    __nv_bfloat16* ql = abf + SM_QL;
    __nv_bfloat16* kh = abf + SM_KH;
    __nv_bfloat16* kl = abf + SM_KL;
    __nv_bfloat16* vh = abf + SM_VH;   // [c][u]
    __nv_bfloat16* vl = abf + SM_VL;
    float* sims_s = (float*)(abf + SM_BF_END);
    int*   idx_s  = (int*)(sims_s + 128);

    int h = blockIdx.x, s = blockIdx.y, b = blockIdx.z;
    int tid = threadIdx.x;              // 256
    int wid = tid >> 5, lane = tid & 31;
    int grp = lane >> 2, tig = lane & 3;
    int wm = wid * 16;
    int base = ((b << 8) + s) << 7;

    if (tid < 128) {
        idx_s[tid]  = g_idx[base + tid];
        sims_s[tid] = g_sims[base + tid];
    }
    __syncthreads();

    int coff = h * DH;
    // gather: 3x 16B loads per (u, 4ch); interleaved layout -> register unpack
    for (int i = tid; i < 1024; i += 256) {
        int u = i >> 3, c = (i & 7) * 4;
        size_t unit = ((size_t)(b * HW + idx_s[u])) * 128 + ((coff + c) >> 1);
        uint4 vq = *(const uint4*)&g_qi[unit * 4];
        uint4 vk = *(const uint4*)&g_ki[unit * 4];
        uint4 vv = *(const uint4*)&g_vi[unit * 4];
        // .x = hi(c,c+1) .y = lo(c,c+1) .z = hi(c+2,c+3) .w = lo(c+2,c+3)
        *(uint2*)&qh[u * QSTR + c] = make_uint2(vq.x, vq.z);
        *(uint2*)&ql[u * QSTR + c] = make_uint2(vq.y, vq.w);
        *(uint2*)&kh[u * QSTR + c] = make_uint2(vk.x, vk.z);
        *(uint2*)&kl[u * QSTR + c] = make_uint2(vk.y, vk.w);
        __nv_bfloat16 th[4], tl[4];
        *(uint32_t*)&th[0] = vv.x; *(uint32_t*)&th[2] = vv.z;
        *(uint32_t*)&tl[0] = vv.y; *(uint32_t*)&tl[2] = vv.w;
#pragma unroll
        for (int j = 0; j < 4; j++) {
            vh[(c + j) * VSTR + u] = th[j];
            vl[(c + j) * VSTR + u] = tl[j];
        }
    }
    __syncthreads();

    // GEMM1: S[wm+.., 128] = Q·K^T (3-product split), acc[16 n-tiles][4]
    float acc[16][4];
#pragma unroll
    for (int nt = 0; nt < 16; nt++)
#pragma unroll
        for (int rgi = 0; rgi < 4; rgi++) acc[nt][rgi] = 0.f;

#pragma unroll
    for (int ks = 0; ks < 2; ks++) {
        int ca = ks * 16 + tig * 2;
        uint32_t ah0 = *(const uint32_t*)&qh[(wm + grp) * QSTR + ca];
        uint32_t ah1 = *(const uint32_t*)&qh[(wm + grp + 8) * QSTR + ca];
        uint32_t ah2 = *(const uint32_t*)&qh[(wm + grp) * QSTR + ca + 8];
        uint32_t ah3 = *(const uint32_t*)&qh[(wm + grp + 8) * QSTR + ca + 8];
        uint32_t al0 = *(const uint32_t*)&ql[(wm + grp) * QSTR + ca];
        uint32_t al1 = *(const uint32_t*)&ql[(wm + grp + 8) * QSTR + ca];
        uint32_t al2 = *(const uint32_t*)&ql[(wm + grp) * QSTR + ca + 8];
        uint32_t al3 = *(const uint32_t*)&ql[(wm + grp + 8) * QSTR + ca + 8];
#pragma unroll
        for (int nt = 0; nt < 16; nt++) {
            int ro = (nt * 8 + grp) * QSTR + ca;
            uint32_t bh0 = *(const uint32_t*)&kh[ro];
            uint32_t bh1 = *(const uint32_t*)&kh[ro + 8];
            uint32_t bl0 = *(const uint32_t*)&kl[ro];
            uint32_t bl1 = *(const uint32_t*)&kl[ro + 8];
            float* c = acc[nt];
            MMA_BF16(c[0], c[1], c[2], c[3], ah0, ah1, ah2, ah3, bh0, bh1);
            MMA_BF16(c[0], c[1], c[2], c[3], ah0, ah1, ah2, ah3, bl0, bl1);
            MMA_BF16(c[0], c[1], c[2], c[3], al0, al1, al2, al3, bh0, bh1);
        }
    }

    // softmax in registers: rows wm+grp (c0,c1) and wm+grp+8 (c2,c3)
    float mx0 = -3.4e38f, mx1 = -3.4e38f;
#pragma unroll
    for (int nt = 0; nt < 16; nt++) {
        mx0 = fmaxf(mx0, fmaxf(acc[nt][0], acc[nt][1]));
        mx1 = fmaxf(mx1, fmaxf(acc[nt][2], acc[nt][3]));
    }
#pragma unroll
    for (int m = 1; m <= 2; m <<= 1) {
        mx0 = fmaxf(mx0, __shfl_xor_sync(0xffffffffu, mx0, m));
        mx1 = fmaxf(mx1, __shfl_xor_sync(0xffffffffu, mx1, m));
    }
    float sum0 = 0.f, sum1 = 0.f;
#pragma unroll
    for (int nt = 0; nt < 16; nt++) {
        acc[nt][0] = __expf(acc[nt][0] - mx0);
        acc[nt][1] = __expf(acc[nt][1] - mx0);
        acc[nt][2] = __expf(acc[nt][2] - mx1);
        acc[nt][3] = __expf(acc[nt][3] - mx1);
        sum0 += acc[nt][0] + acc[nt][1];
        sum1 += acc[nt][2] + acc[nt][3];
    }
#pragma unroll
    for (int m = 1; m <= 2; m <<= 1) {
        sum0 += __shfl_xor_sync(0xffffffffu, sum0, m);
        sum1 += __shfl_xor_sync(0xffffffffu, sum1, m);
    }

    // GEMM2: O = (P .* sims[u]) · V, P from acc regs (sims folded per-column)
    float ot[4][4];
#pragma unroll
    for (int nt = 0; nt < 4; nt++)
#pragma unroll
        for (int rgi = 0; rgi < 4; rgi++) ot[nt][rgi] = 0.f;

#pragma unroll
    for (int ks = 0; ks < 8; ks++) {
        float* t0 = acc[2 * ks];
        float* t1 = acc[2 * ks + 1];
        float w00 = sims_s[ks * 16 + tig * 2];
        float w01 = sims_s[ks * 16 + tig * 2 + 1];
        float w10 = sims_s[ks * 16 + 8 + tig * 2];
        float w11 = sims_s[ks * 16 + 8 + tig * 2 + 1];
        float p00 = t0[0] * w00, p01 = t0[1] * w01;
        float p02 = t0[2] * w00, p03 = t0[3] * w01;
        float p10 = t1[0] * w10, p11 = t1[1] * w11;
        float p12 = t1[2] * w10, p13 = t1[3] * w11;
        __nv_bfloat16 h00 = __float2bfloat16(p00), h01 = __float2bfloat16(p01);
        __nv_bfloat16 h02 = __float2bfloat16(p02), h03 = __float2bfloat16(p03);
        __nv_bfloat16 h10 = __float2bfloat16(p10), h11 = __float2bfloat16(p11);
        __nv_bfloat16 h12 = __float2bfloat16(p12), h13 = __float2bfloat16(p13);
        uint32_t ah0 = pk2(h00, h01), ah1 = pk2(h02, h03);
        uint32_t ah2 = pk2(h10, h11), ah3 = pk2(h12, h13);
        uint32_t al0 = pk2(__float2bfloat16(p00 - __bfloat162float(h00)),
                           __float2bfloat16(p01 - __bfloat162float(h01)));
        uint32_t al1 = pk2(__float2bfloat16(p02 - __bfloat162float(h02)),
                           __float2bfloat16(p03 - __bfloat162float(h03)));
        uint32_t al2 = pk2(__float2bfloat16(p10 - __bfloat162float(h10)),
                           __float2bfloat16(p11 - __bfloat162float(h11)));
        uint32_t al3 = pk2(__float2bfloat16(p12 - __bfloat162float(h12)),
                           __float2bfloat16(p13 - __bfloat162float(h13)));
        int ub = ks * 16 + tig * 2;
#pragma unroll
        for (int nt = 0; nt < 4; nt++) {
            int bo = (nt * 8 + grp) * VSTR + ub;
            uint32_t bh0 = *(const uint32_t*)&vh[bo];
            uint32_t bh1 = *(const uint32_t*)&vh[bo + 8];
            uint32_t bl0 = *(const uint32_t*)&vl[bo];
            uint32_t bl1 = *(const uint32_t*)&vl[bo + 8];
            float* c = ot[nt];
            MMA_BF16(c[0], c[1], c[2], c[3], ah0, ah1, ah2, ah3, bh0, bh1);
            MMA_BF16(c[0], c[1], c[2], c[3], ah0, ah1, ah2, ah3, bl0, bl1);
            MMA_BF16(c[0], c[1], c[2], c[3], al0, al1, al2, al3, bh0, bh1);
        }
    }

    // scatter with row scale sims/sum
    {
        int r0 = wm + grp, r1 = wm + grp + 8;
        float rs0 = sims_s[r0] / sum0;
        float rs1 = sims_s[r1] / sum1;
        int n0 = idx_s[r0], n1 = idx_s[r1];
        float* rp = res + ((size_t)b * CC + coff) * HW;
#pragma unroll
        for (int nt = 0; nt < 4; nt++) {
            int c0 = nt * 8 + tig * 2;
            atomicAdd(rp + (size_t)c0 * HW + n0,       ot[nt][0] * rs0);
            atomicAdd(rp + (size_t)(c0 + 1) * HW + n0, ot[nt][1] * rs0);
            atomicAdd(rp + (size_t)c0 * HW + n1,       ot[nt][2] * rs1);
            atomicAdd(rp + (size_t)(c0 + 1) * HW + n1, ot[nt][3] * rs1);
        }
    }
}

// ---------------- launch ----------------
extern "C" void kernel_launch(void* const* d_in, const int* in_sizes, int n_in,
                              void* d_out, int out_size) {
    const float* x   = (const float*)d_in[0];
    const float* aff = (const float*)d_in[1];
    const float* lnw = (const float*)d_in[2];
    const float* lnb = (const float*)d_in[3];
    const float* wq  = (const float*)d_in[4];
    const float* wk  = (const float*)d_in[5];
    const float* wv  = (const float*)d_in[6];
    float* out = (float*)d_out;

    cudaFuncSetAttribute(topk_kernel, cudaFuncAttributeMaxDynamicSharedMemorySize, TOPK_SMEM);
    cudaFuncSetAttribute(attn_kernel, cudaFuncAttributeMaxDynamicSharedMemorySize, ATTN_SMEM);
    cudaFuncSetAttribute(gemm_tc_kernel, cudaFuncAttributeMaxDynamicSharedMemorySize, GT_SMEM);

    ln_kernel<<<1024, 256>>>(x, lnw, lnb);
    wsplit_kernel<<<768, 256>>>(wq, wk, wv);
    gemm_tc_kernel<<<dim3(256, 2, 3), 256, GT_SMEM>>>(out);
    topk_kernel<<<BB * SS, TK_THR, TOPK_SMEM>>>(aff);
    attn_kernel<<<dim3(NH, SS, BB), 256, ATTN_SMEM>>>(out);
}

// round 14
// speedup vs baseline: 1.1548x; 1.0841x over previous
#include <cuda_runtime.h>
#include <cuda_bf16.h>
#include <cstdint>

// Problem constants
#define BB 2
#define CC 256
#define HW 16384
#define SS 256
#define TT 128
#define NH 8
#define DH 32
#define SCALE 0.17677669529663689f   // 32^-0.5
#define LN_EPS 1e-5f

typedef unsigned long long u64;

// warp-level bf16 MMA, m16n8k16, fp32 accumulate (baseline PTX)
#define MMA_BF16(c0,c1,c2,c3, a0,a1,a2,a3, b0,b1) \
    asm("mma.sync.aligned.m16n8k16.row.col.f32.bf16.bf16.f32 " \
        "{%0,%1,%2,%3}, {%4,%5,%6,%7}, {%8,%9}, {%0,%1,%2,%3};" \
        : "+f"(c0), "+f"(c1), "+f"(c2), "+f"(c3) \
        : "r"(a0), "r"(a1), "r"(a2), "r"(a3), "r"(b0), "r"(b1))

__device__ __forceinline__ uint32_t pk2(__nv_bfloat16 a, __nv_bfloat16 b) {
    unsigned short ua = *(unsigned short*)&a, ub = *(unsigned short*)&b;
    return (uint32_t)ua | ((uint32_t)ub << 16);
}

// ---------------- scratch (device globals; no allocation allowed) ----------------
__device__ __nv_bfloat16 g_xh[(size_t)BB * HW * CC];  // LN output hi bf16, [m][c]
__device__ __nv_bfloat16 g_xl[(size_t)BB * HW * CC];  // LN output lo bf16
__device__ __nv_bfloat16 g_wh[3 * CC * CC];           // W hi bf16 (wq pre-scaled)
__device__ __nv_bfloat16 g_wl[3 * CC * CC];
// projections, split bf16 interleaved: unit p = channel pair, layout
// [m][p] -> 4 bf16: {hi(2p), hi(2p+1), lo(2p), lo(2p+1)}  (8 bytes per unit)
__device__ __nv_bfloat16 g_qi[(size_t)BB * HW * CC * 2];
__device__ __nv_bfloat16 g_ki[(size_t)BB * HW * CC * 2];
__device__ __nv_bfloat16 g_vi[(size_t)BB * HW * CC * 2];
__device__ float g_acc[(size_t)BB * HW * CC];   // pixel-major accumulator [b][n][c]
__device__ float g_sims[(size_t)BB * SS * TT];
__device__ int   g_idx [(size_t)BB * SS * TT];

// ---------------- zero the accumulator -------------------------------------------
__global__ void zero_kernel() {
    size_t i = ((size_t)blockIdx.x * 256 + threadIdx.x) * 4;
    *(float4*)&g_acc[i] = make_float4(0.f, 0.f, 0.f, 0.f);
}

// ---------------- LayerNorm: x (B,C,H,W) -> split bf16 (B,HW,C) -------------------
__global__ void ln_kernel(const float* __restrict__ x,
                          const float* __restrict__ lnw,
                          const float* __restrict__ lnb) {
    __shared__ float tile[256][33];
    __shared__ float red_s[8][32], red_ss[8][32];
    __shared__ float s_mean[32], s_inv[32];

    int blk = blockIdx.x;            // 1024 blocks, 512 per batch
    int b   = blk >> 9;
    int n0  = (blk & 511) * 32;
    int tid = threadIdx.x;           // 256
    int tn  = tid & 31;
    int cg  = tid >> 5;              // warp id 0..7

    const float* xb = x + (size_t)b * CC * HW;

#pragma unroll 8
    for (int r = 0; r < 32; r++) {
        int c = r * 8 + cg;
        tile[c][tn] = xb[(size_t)c * HW + n0 + tn];
    }
    __syncthreads();

    float s = 0.f, ss = 0.f;
#pragma unroll 8
    for (int j = 0; j < 32; j++) {
        float v = tile[cg * 32 + j][tn];
        s += v; ss += v * v;
    }
    red_s[cg][tn] = s; red_ss[cg][tn] = ss;
    __syncthreads();
    if (cg == 0) {
        float S = 0.f, SSU = 0.f;
#pragma unroll
        for (int j = 0; j < 8; j++) { S += red_s[j][tn]; SSU += red_ss[j][tn]; }
        float m   = S * (1.0f / 256.0f);
        float var = SSU * (1.0f / 256.0f) - m * m;
        s_mean[tn] = m;
        s_inv[tn]  = rsqrtf(var + LN_EPS);
    }
    __syncthreads();

    float wv = lnw[tid], bv = lnb[tid];
    size_t rb = (size_t)(b * HW + n0) * CC + tid;
#pragma unroll 8
    for (int it = 0; it < 32; it++) {
        float v = tile[tid][it];
        float y = (v - s_mean[it]) * s_inv[it] * wv + bv;
        __nv_bfloat16 hi = __float2bfloat16(y);
        g_xh[rb + (size_t)it * CC] = hi;
        g_xl[rb + (size_t)it * CC] = __float2bfloat16(y - __bfloat162float(hi));
    }
}

// ---------------- split weights into bf16 hi/lo (SCALE folded into wq) -----------
__global__ void wsplit_kernel(const float* __restrict__ Wq,
                              const float* __restrict__ Wk,
                              const float* __restrict__ Wv) {
    int i = blockIdx.x * 256 + threadIdx.x;        // 0 .. 3*65536-1
    int mat = i >> 16, j = i & 65535;
    const float* W = (mat == 0) ? Wq : ((mat == 1) ? Wk : Wv);
    float f = W[j];
    if (mat == 0) f *= SCALE;
    __nv_bfloat16 hi = __float2bfloat16(f);
    g_wh[i] = hi;
    g_wl[i] = __float2bfloat16(f - __bfloat162float(hi));
}

// ---------------- projection GEMM on HMMA (mma.sync, split-bf16 3-product) --------
// Outputs interleaved split bf16 q/k/v.
#define STRA 40                         // smem row stride (bf16 units)
#define GT_SMEM (4 * 128 * STRA * 2)    // Ah, Al, Bh, Bl tiles

__global__ void __launch_bounds__(256, 1) gemm_tc_kernel() {
    extern __shared__ __nv_bfloat16 sm_bf[];
    __nv_bfloat16* Ah = sm_bf;
    __nv_bfloat16* Al = Ah + 128 * STRA;
    __nv_bfloat16* Bh = Al + 128 * STRA;
    __nv_bfloat16* Bl = Bh + 128 * STRA;

    int mat = blockIdx.z;
    __nv_bfloat16* Oi = (mat == 0) ? g_qi : ((mat == 1) ? g_ki : g_vi);
    size_t bm = (size_t)blockIdx.x * 128;
    int bn = blockIdx.y * 128;

    int tid = threadIdx.x;
    int wid = tid >> 5, lane = tid & 31;
    int grp = lane >> 2, tig = lane & 3;
    int wm = (wid & 1) * 64, wn = (wid >> 1) * 32;

    const __nv_bfloat16* wh_b = g_wh + (size_t)mat * 65536;
    const __nv_bfloat16* wl_b = g_wl + (size_t)mat * 65536;

    int lr = tid >> 1, lh = tid & 1;
    const uint4* pAh = (const uint4*)(g_xh + (bm + lr) * 256 + lh * 16);
    const uint4* pAl = (const uint4*)(g_xl + (bm + lr) * 256 + lh * 16);
    const uint4* pBh = (const uint4*)(wh_b + (size_t)(bn + lr) * 256 + lh * 16);
    const uint4* pBl = (const uint4*)(wl_b + (size_t)(bn + lr) * 256 + lh * 16);
    int soff = lr * STRA + lh * 16;

    float acc[4][4][4];
#pragma unroll
    for (int mi = 0; mi < 4; mi++)
#pragma unroll
        for (int ni = 0; ni < 4; ni++)
#pragma unroll
            for (int rgi = 0; rgi < 4; rgi++) acc[mi][ni][rgi] = 0.f;

    uint4 rAh[2], rAl[2], rBh[2], rBl[2];
#pragma unroll
    for (int q = 0; q < 2; q++) {
        rAh[q] = pAh[q]; rAl[q] = pAl[q];
        rBh[q] = pBh[q]; rBl[q] = pBl[q];
    }

#pragma unroll 1
    for (int chunk = 0; chunk < 8; chunk++) {
#pragma unroll
        for (int q = 0; q < 2; q++) {
            *(uint4*)(Ah + soff + q * 8) = rAh[q];
            *(uint4*)(Al + soff + q * 8) = rAl[q];
            *(uint4*)(Bh + soff + q * 8) = rBh[q];
            *(uint4*)(Bl + soff + q * 8) = rBl[q];
        }
        __syncthreads();

        int nc = (chunk < 7) ? (chunk + 1) : 7;
        int gofs = nc * 4;
#pragma unroll
        for (int q = 0; q < 2; q++) {
            rAh[q] = pAh[gofs + q]; rAl[q] = pAl[gofs + q];
            rBh[q] = pBh[gofs + q]; rBl[q] = pBl[gofs + q];
        }

#pragma unroll
        for (int ks = 0; ks < 32; ks += 16) {
            uint32_t ah[4][4], al[4][4], bh[4][2], bl[4][2];
            int ca = ks + tig * 2;
#pragma unroll
            for (int mi = 0; mi < 4; mi++) {
                int r0 = wm + mi * 16 + grp;
                ah[mi][0] = *(const uint32_t*)(Ah + r0 * STRA + ca);
                ah[mi][1] = *(const uint32_t*)(Ah + (r0 + 8) * STRA + ca);
                ah[mi][2] = *(const uint32_t*)(Ah + r0 * STRA + ca + 8);
                ah[mi][3] = *(const uint32_t*)(Ah + (r0 + 8) * STRA + ca + 8);
                al[mi][0] = *(const uint32_t*)(Al + r0 * STRA + ca);
                al[mi][1] = *(const uint32_t*)(Al + (r0 + 8) * STRA + ca);
                al[mi][2] = *(const uint32_t*)(Al + r0 * STRA + ca + 8);
                al[mi][3] = *(const uint32_t*)(Al + (r0 + 8) * STRA + ca + 8);
            }
#pragma unroll
            for (int ni = 0; ni < 4; ni++) {
                int n0 = wn + ni * 8 + grp;
                bh[ni][0] = *(const uint32_t*)(Bh + n0 * STRA + ca);
                bh[ni][1] = *(const uint32_t*)(Bh + n0 * STRA + ca + 8);
                bl[ni][0] = *(const uint32_t*)(Bl + n0 * STRA + ca);
                bl[ni][1] = *(const uint32_t*)(Bl + n0 * STRA + ca + 8);
            }
#pragma unroll
            for (int mi = 0; mi < 4; mi++)
#pragma unroll
                for (int ni = 0; ni < 4; ni++) {
                    float* c = acc[mi][ni];
                    MMA_BF16(c[0], c[1], c[2], c[3],
                             ah[mi][0], ah[mi][1], ah[mi][2], ah[mi][3],
                             bh[ni][0], bh[ni][1]);
                    MMA_BF16(c[0], c[1], c[2], c[3],
                             ah[mi][0], ah[mi][1], ah[mi][2], ah[mi][3],
                             bl[ni][0], bl[ni][1]);
                    MMA_BF16(c[0], c[1], c[2], c[3],
                             al[mi][0], al[mi][1], al[mi][2], al[mi][3],
                             bh[ni][0], bh[ni][1]);
                }
        }
        __syncthreads();
    }

    // epilogue: interleaved split store — one uint2 per (row, channel-pair)
#pragma unroll
    for (int mi = 0; mi < 4; mi++) {
#pragma unroll
        for (int ni = 0; ni < 4; ni++) {
            float* c = acc[mi][ni];
            size_t row0 = bm + wm + mi * 16 + grp;
            size_t row1 = row0 + 8;
            int col = bn + wn + ni * 8 + tig * 2;   // even channel pair base
            __nv_bfloat16 h0 = __float2bfloat16(c[0]);
            __nv_bfloat16 h1 = __float2bfloat16(c[1]);
            __nv_bfloat16 h2 = __float2bfloat16(c[2]);
            __nv_bfloat16 h3 = __float2bfloat16(c[3]);
            uint2 v0, v1;
            v0.x = pk2(h0, h1);
            v0.y = pk2(__float2bfloat16(c[0] - __bfloat162float(h0)),
                       __float2bfloat16(c[1] - __bfloat162float(h1)));
            v1.x = pk2(h2, h3);
            v1.y = pk2(__float2bfloat16(c[2] - __bfloat162float(h2)),
                       __float2bfloat16(c[3] - __bfloat162float(h3)));
            *(uint2*)&Oi[(row0 * 128 + (col >> 1)) * 4] = v0;
            *(uint2*)&Oi[(row1 * 128 + (col >> 1)) * 4] = v1;
        }
    }
}

// ---------------- top-k: per (b,s) row of 16384, select top-128 (radix select) ----
// 512 threads, 4-way replicated histogram, parallel suffix-scan bin selection.
#define TK_N 16384
#define TK_THR 512
#define TOPK_SMEM ((TK_N + 1024 + 256) * 4)
__global__ void __launch_bounds__(TK_THR) topk_kernel(const float* __restrict__ aff) {
    extern __shared__ unsigned int shm[];
    unsigned int* keys  = shm;               // 16384
    unsigned int* hist  = shm + TK_N;        // 4 copies x 256
    unsigned int* sscan = hist + 1024;       // 256
    __shared__ unsigned int s_prefix, s_rem, s_cntgt, s_cnteq, s_sel, s_gt;
    __shared__ int eq_idx[128];

    int row = blockIdx.x;
    const float* ap = aff + (size_t)row * TK_N;
    int tid = threadIdx.x;
    int hcp = (tid >> 5) & 3;                // histogram copy = warp % 4

    for (int n = tid; n < TK_N; n += TK_THR) {
        unsigned int u = __float_as_uint(ap[n]);
        keys[n] = (u & 0x80000000u) ? ~u : (u | 0x80000000u);
    }
    if (tid == 0) { s_prefix = 0u; s_rem = 128u; s_cntgt = 0u; s_cnteq = 0u; }
    __syncthreads();

    for (int sh = 24; sh >= 0; sh -= 8) {
        for (int i = tid; i < 1024; i += TK_THR) hist[i] = 0u;
        __syncthreads();
        unsigned int pref = s_prefix, rem = s_rem;
        unsigned int mask = (sh == 24) ? 0u : (0xFFFFFFFFu << (sh + 8));
#pragma unroll 8
        for (int n = tid; n < TK_N; n += TK_THR) {
            unsigned int k = keys[n];
            if (((k ^ pref) & mask) == 0u)
                atomicAdd(&hist[hcp * 256 + ((k >> sh) & 0xFF)], 1u);
        }
        __syncthreads();
        if (tid < 256)
            sscan[tid] = hist[tid] + hist[256 + tid] + hist[512 + tid] + hist[768 + tid];
        __syncthreads();
        // suffix sum: sscan[b] = count of keys with byte >= b (within prefix)
#pragma unroll
        for (int off = 1; off < 256; off <<= 1) {
            unsigned int v = 0u, a = 0u;
            if (tid < 256) { v = sscan[tid]; if (tid + off < 256) a = sscan[tid + off]; }
            __syncthreads();
            if (tid < 256) sscan[tid] = v + a;
            __syncthreads();
        }
        if (tid < 256) {
            unsigned int ge = sscan[tid];
            unsigned int gt = (tid < 255) ? sscan[tid + 1] : 0u;
            if (ge >= rem && gt < rem) { s_sel = (unsigned int)tid; s_gt = gt; }
        }
        __syncthreads();
        if (tid == 0) {
            s_prefix = pref | (s_sel << sh);
            s_rem = rem - s_gt;
        }
        __syncthreads();
    }

    unsigned int thr = s_prefix;
    int take_eq = (int)s_rem;
    int n_gt = 128 - take_eq;

    for (int n = tid; n < TK_N; n += TK_THR) {
        unsigned int k = keys[n];
        if (k > thr) {
            int p = (int)atomicAdd(&s_cntgt, 1u);
            g_idx[(size_t)row * 128 + p]  = n;
            g_sims[(size_t)row * 128 + p] = ap[n];
        } else if (k == thr) {
            int e = (int)atomicAdd(&s_cnteq, 1u);
            if (e < 128) eq_idx[e] = n;
        }
    }
    __syncthreads();
    if (tid == 0) {
        int ne = (int)s_cnteq; if (ne > 128) ne = 128;
        // sort ascending so ties break toward lowest index (matches lax.top_k)
        for (int i = 1; i < ne; i++) {
            int v = eq_idx[i]; int j = i - 1;
            while (j >= 0 && eq_idx[j] > v) { eq_idx[j + 1] = eq_idx[j]; j--; }
            eq_idx[j + 1] = v;
        }
        for (int i = 0; i < take_eq; i++) {
            int src = (i < ne) ? i : (ne - 1);
            int n = eq_idx[src];
            g_idx[(size_t)row * 128 + n_gt + i]  = n;
            g_sims[(size_t)row * 128 + n_gt + i] = ap[n];
        }
    }
}

// ---------------- attention per (head, s, b) — HMMA split-bf16 --------------------
// smem bf16: qh/ql/kh/kl [128][40], vh/vl transposed [32][136]; + sims/idx
#define QSTR 40
#define VSTR 136
#define SM_QH 0
#define SM_QL (SM_QH + 128 * QSTR)
#define SM_KH (SM_QL + 128 * QSTR)
#define SM_KL (SM_KH + 128 * QSTR)
#define SM_VH (SM_KL + 128 * QSTR)
#define SM_VL (SM_VH + 32 * VSTR)
#define SM_BF_END (SM_VL + 32 * VSTR)
#define ATTN_SMEM (SM_BF_END * 2 + 128 * 8)

__global__ void __launch_bounds__(256) attn_kernel() {
    extern __shared__ __nv_bfloat16 abf[];
    __nv_bfloat16* qh = abf + SM_QH;
    __nv_bfloat16* ql = abf + SM_QL;
    __nv_bfloat16* kh = abf + SM_KH;
    __nv_bfloat16* kl = abf + SM_KL;
    __nv_bfloat16* vh = abf + SM_VH;   // [c][u]
    __nv_bfloat16* vl = abf + SM_VL;
    float* sims_s = (float*)(abf + SM_BF_END);
    int*   idx_s  = (int*)(sims_s + 128);

    int h = blockIdx.x, s = blockIdx.y, b = blockIdx.z;
    int tid = threadIdx.x;              // 256
    int wid = tid >> 5, lane = tid & 31;
    int grp = lane >> 2, tig = lane & 3;
    int wm = wid * 16;
    int base = ((b << 8) + s) << 7;

    if (tid < 128) {
        idx_s[tid]  = g_idx[base + tid];
        sims_s[tid] = g_sims[base + tid];
    }
    __syncthreads();

    int coff = h * DH;
    // gather: 3x 16B loads per (u, 4ch); interleaved layout -> register unpack
    for (int i = tid; i < 1024; i += 256) {
        int u = i >> 3, c = (i & 7) * 4;
        size_t unit = ((size_t)(b * HW + idx_s[u])) * 128 + ((coff + c) >> 1);
        uint4 vq = *(const uint4*)&g_qi[unit * 4];
        uint4 vk = *(const uint4*)&g_ki[unit * 4];
        uint4 vv = *(const uint4*)&g_vi[unit * 4];
        // .x = hi(c,c+1) .y = lo(c,c+1) .z = hi(c+2,c+3) .w = lo(c+2,c+3)
        *(uint2*)&qh[u * QSTR + c] = make_uint2(vq.x, vq.z);
        *(uint2*)&ql[u * QSTR + c] = make_uint2(vq.y, vq.w);
        *(uint2*)&kh[u * QSTR + c] = make_uint2(vk.x, vk.z);
        *(uint2*)&kl[u * QSTR + c] = make_uint2(vk.y, vk.w);
        __nv_bfloat16 th[4], tl[4];
        *(uint32_t*)&th[0] = vv.x; *(uint32_t*)&th[2] = vv.z;
        *(uint32_t*)&tl[0] = vv.y; *(uint32_t*)&tl[2] = vv.w;
#pragma unroll
        for (int j = 0; j < 4; j++) {
            vh[(c + j) * VSTR + u] = th[j];
            vl[(c + j) * VSTR + u] = tl[j];
        }
    }
    __syncthreads();

    // GEMM1: S[wm+.., 128] = Q·K^T (3-product split), acc[16 n-tiles][4]
    float acc[16][4];
#pragma unroll
    for (int nt = 0; nt < 16; nt++)
#pragma unroll
        for (int rgi = 0; rgi < 4; rgi++) acc[nt][rgi] = 0.f;

#pragma unroll
    for (int ks = 0; ks < 2; ks++) {
        int ca = ks * 16 + tig * 2;
        uint32_t ah0 = *(const uint32_t*)&qh[(wm + grp) * QSTR + ca];
        uint32_t ah1 = *(const uint32_t*)&qh[(wm + grp + 8) * QSTR + ca];
        uint32_t ah2 = *(const uint32_t*)&qh[(wm + grp) * QSTR + ca + 8];
        uint32_t ah3 = *(const uint32_t*)&qh[(wm + grp + 8) * QSTR + ca + 8];
        uint32_t al0 = *(const uint32_t*)&ql[(wm + grp) * QSTR + ca];
        uint32_t al1 = *(const uint32_t*)&ql[(wm + grp + 8) * QSTR + ca];
        uint32_t al2 = *(const uint32_t*)&ql[(wm + grp) * QSTR + ca + 8];
        uint32_t al3 = *(const uint32_t*)&ql[(wm + grp + 8) * QSTR + ca + 8];
#pragma unroll
        for (int nt = 0; nt < 16; nt++) {
            int ro = (nt * 8 + grp) * QSTR + ca;
            uint32_t bh0 = *(const uint32_t*)&kh[ro];
            uint32_t bh1 = *(const uint32_t*)&kh[ro + 8];
            uint32_t bl0 = *(const uint32_t*)&kl[ro];
            uint32_t bl1 = *(const uint32_t*)&kl[ro + 8];
            float* c = acc[nt];
            MMA_BF16(c[0], c[1], c[2], c[3], ah0, ah1, ah2, ah3, bh0, bh1);
            MMA_BF16(c[0], c[1], c[2], c[3], ah0, ah1, ah2, ah3, bl0, bl1);
            MMA_BF16(c[0], c[1], c[2], c[3], al0, al1, al2, al3, bh0, bh1);
        }
    }

    // softmax in registers: rows wm+grp (c0,c1) and wm+grp+8 (c2,c3)
    float mx0 = -3.4e38f, mx1 = -3.4e38f;
#pragma unroll
    for (int nt = 0; nt < 16; nt++) {
        mx0 = fmaxf(mx0, fmaxf(acc[nt][0], acc[nt][1]));
        mx1 = fmaxf(mx1, fmaxf(acc[nt][2], acc[nt][3]));
    }
#pragma unroll
    for (int m = 1; m <= 2; m <<= 1) {
        mx0 = fmaxf(mx0, __shfl_xor_sync(0xffffffffu, mx0, m));
        mx1 = fmaxf(mx1, __shfl_xor_sync(0xffffffffu, mx1, m));
    }
    float sum0 = 0.f, sum1 = 0.f;
#pragma unroll
    for (int nt = 0; nt < 16; nt++) {
        acc[nt][0] = __expf(acc[nt][0] - mx0);
        acc[nt][1] = __expf(acc[nt][1] - mx0);
        acc[nt][2] = __expf(acc[nt][2] - mx1);
        acc[nt][3] = __expf(acc[nt][3] - mx1);
        sum0 += acc[nt][0] + acc[nt][1];
        sum1 += acc[nt][2] + acc[nt][3];
    }
#pragma unroll
    for (int m = 1; m <= 2; m <<= 1) {
        sum0 += __shfl_xor_sync(0xffffffffu, sum0, m);
        sum1 += __shfl_xor_sync(0xffffffffu, sum1, m);
    }

    // GEMM2: O = (P .* sims[u]) · V, P from acc regs (sims folded per-column)
    float ot[4][4];
#pragma unroll
    for (int nt = 0; nt < 4; nt++)
#pragma unroll
        for (int rgi = 0; rgi < 4; rgi++) ot[nt][rgi] = 0.f;

#pragma unroll
    for (int ks = 0; ks < 8; ks++) {
        float* t0 = acc[2 * ks];
        float* t1 = acc[2 * ks + 1];
        float w00 = sims_s[ks * 16 + tig * 2];
        float w01 = sims_s[ks * 16 + tig * 2 + 1];
        float w10 = sims_s[ks * 16 + 8 + tig * 2];
        float w11 = sims_s[ks * 16 + 8 + tig * 2 + 1];
        float p00 = t0[0] * w00, p01 = t0[1] * w01;
        float p02 = t0[2] * w00, p03 = t0[3] * w01;
        float p10 = t1[0] * w10, p11 = t1[1] * w11;
        float p12 = t1[2] * w10, p13 = t1[3] * w11;
        __nv_bfloat16 h00 = __float2bfloat16(p00), h01 = __float2bfloat16(p01);
        __nv_bfloat16 h02 = __float2bfloat16(p02), h03 = __float2bfloat16(p03);
        __nv_bfloat16 h10 = __float2bfloat16(p10), h11 = __float2bfloat16(p11);
        __nv_bfloat16 h12 = __float2bfloat16(p12), h13 = __float2bfloat16(p13);
        uint32_t ah0 = pk2(h00, h01), ah1 = pk2(h02, h03);
        uint32_t ah2 = pk2(h10, h11), ah3 = pk2(h12, h13);
        uint32_t al0 = pk2(__float2bfloat16(p00 - __bfloat162float(h00)),
                           __float2bfloat16(p01 - __bfloat162float(h01)));
        uint32_t al1 = pk2(__float2bfloat16(p02 - __bfloat162float(h02)),
                           __float2bfloat16(p03 - __bfloat162float(h03)));
        uint32_t al2 = pk2(__float2bfloat16(p10 - __bfloat162float(h10)),
                           __float2bfloat16(p11 - __bfloat162float(h11)));
        uint32_t al3 = pk2(__float2bfloat16(p12 - __bfloat162float(h12)),
                           __float2bfloat16(p13 - __bfloat162float(h13)));
        int ub = ks * 16 + tig * 2;
#pragma unroll
        for (int nt = 0; nt < 4; nt++) {
            int bo = (nt * 8 + grp) * VSTR + ub;
            uint32_t bh0 = *(const uint32_t*)&vh[bo];
            uint32_t bh1 = *(const uint32_t*)&vh[bo + 8];
            uint32_t bl0 = *(const uint32_t*)&vl[bo];
            uint32_t bl1 = *(const uint32_t*)&vl[bo + 8];
            float* c = ot[nt];
            MMA_BF16(c[0], c[1], c[2], c[3], ah0, ah1, ah2, ah3, bh0, bh1);
            MMA_BF16(c[0], c[1], c[2], c[3], ah0, ah1, ah2, ah3, bl0, bl1);
            MMA_BF16(c[0], c[1], c[2], c[3], al0, al1, al2, al3, bh0, bh1);
        }
    }

    // scatter with row scale sims/sum -> pixel-major accumulator (coalesced sectors)
    {
        int r0 = wm + grp, r1 = wm + grp + 8;
        float rs0 = sims_s[r0] / sum0;
        float rs1 = sims_s[r1] / sum1;
        size_t n0 = (size_t)(b * HW + idx_s[r0]) * 256 + coff;
        size_t n1 = (size_t)(b * HW + idx_s[r1]) * 256 + coff;
#pragma unroll
        for (int nt = 0; nt < 4; nt++) {
            int c0 = nt * 8 + tig * 2;
            atomicAdd(&g_acc[n0 + c0],     ot[nt][0] * rs0);
            atomicAdd(&g_acc[n0 + c0 + 1], ot[nt][1] * rs0);
            atomicAdd(&g_acc[n1 + c0],     ot[nt][2] * rs1);
            atomicAdd(&g_acc[n1 + c0 + 1], ot[nt][3] * rs1);
        }
    }
}

// ---------------- final: out[b][c][n] = g_acc[b][n][c] + v(n,c) -------------------
__global__ void final_kernel(float* __restrict__ out) {
    __shared__ float t[32][33];
    int n0 = blockIdx.x * 32, c0 = blockIdx.y * 32, b = blockIdx.z;
    int tx = threadIdx.x;   // 0..7  channel quad (read phase)
    int ty = threadIdx.y;   // 0..31 row (read phase)

    size_t roff = (size_t)(b * HW + n0 + ty);
    int c = c0 + tx * 4;
    uint4 vv = *(const uint4*)&g_vi[(roff * 128 + (c >> 1)) * 4];
    float4 av = *(const float4*)&g_acc[roff * 256 + c];
    __nv_bfloat16 th[4], tl[4];
    *(uint32_t*)&th[0] = vv.x; *(uint32_t*)&th[2] = vv.z;
    *(uint32_t*)&tl[0] = vv.y; *(uint32_t*)&tl[2] = vv.w;
    t[tx * 4 + 0][ty] = av.x + __bfloat162float(th[0]) + __bfloat162float(tl[0]);
    t[tx * 4 + 1][ty] = av.y + __bfloat162float(th[1]) + __bfloat162float(tl[1]);
    t[tx * 4 + 2][ty] = av.z + __bfloat162float(th[2]) + __bfloat162float(tl[2]);
    t[tx * 4 + 3][ty] = av.w + __bfloat162float(th[3]) + __bfloat162float(tl[3]);
    __syncthreads();

    int tid = ty * 8 + tx;
    int wtx = tid & 31, wty = tid >> 5;   // n offset, c group
#pragma unroll
    for (int j = wty; j < 32; j += 8)
        out[((size_t)b * CC + c0 + j) * HW + n0 + wtx] = t[j][wtx];
}

// ---------------- launch ----------------
extern "C" void kernel_launch(void* const* d_in, const int* in_sizes, int n_in,
                              void* d_out, int out_size) {
    const float* x   = (const float*)d_in[0];
    const float* aff = (const float*)d_in[1];
    const float* lnw = (const float*)d_in[2];
    const float* lnb = (const float*)d_in[3];
    const float* wq  = (const float*)d_in[4];
    const float* wk  = (const float*)d_in[5];
    const float* wv  = (const float*)d_in[6];
    float* out = (float*)d_out;

    cudaFuncSetAttribute(topk_kernel, cudaFuncAttributeMaxDynamicSharedMemorySize, TOPK_SMEM);
    cudaFuncSetAttribute(attn_kernel, cudaFuncAttributeMaxDynamicSharedMemorySize, ATTN_SMEM);
    cudaFuncSetAttribute(gemm_tc_kernel, cudaFuncAttributeMaxDynamicSharedMemorySize, GT_SMEM);

    zero_kernel<<<(BB * HW * CC) / (256 * 4), 256>>>();
    ln_kernel<<<1024, 256>>>(x, lnw, lnb);
    wsplit_kernel<<<768, 256>>>(wq, wk, wv);
    gemm_tc_kernel<<<dim3(256, 2, 3), 256, GT_SMEM>>>();
    topk_kernel<<<BB * SS, TK_THR, TOPK_SMEM>>>(aff);
    attn_kernel<<<dim3(NH, SS, BB), 256, ATTN_SMEM>>>();
    final_kernel<<<dim3(HW / 32, CC / 32, BB), dim3(8, 32)>>>(out);
}

// round 15
// speedup vs baseline: 1.1549x; 1.0001x over previous
#include <cuda_runtime.h>
#include <cuda_bf16.h>
#include <cstdint>

// Problem constants
#define BB 2
#define CC 256
#define HW 16384
#define SS 256
#define TT 128
#define NH 8
#define DH 32
#define SCALE 0.17677669529663689f   // 32^-0.5
#define LN_EPS 1e-5f

typedef unsigned long long u64;

// warp-level bf16 MMA, m16n8k16, fp32 accumulate (baseline PTX)
#define MMA_BF16(c0,c1,c2,c3, a0,a1,a2,a3, b0,b1) \
    asm("mma.sync.aligned.m16n8k16.row.col.f32.bf16.bf16.f32 " \
        "{%0,%1,%2,%3}, {%4,%5,%6,%7}, {%8,%9}, {%0,%1,%2,%3};" \
        : "+f"(c0), "+f"(c1), "+f"(c2), "+f"(c3) \
        : "r"(a0), "r"(a1), "r"(a2), "r"(a3), "r"(b0), "r"(b1))

__device__ __forceinline__ uint32_t pk2(__nv_bfloat16 a, __nv_bfloat16 b) {
    unsigned short ua = *(unsigned short*)&a, ub = *(unsigned short*)&b;
    return (uint32_t)ua | ((uint32_t)ub << 16);
}

// ---------------- scratch (device globals; no allocation allowed) ----------------
__device__ __nv_bfloat16 g_xh[(size_t)BB * HW * CC];  // LN output hi bf16, [m][c]
__device__ __nv_bfloat16 g_xl[(size_t)BB * HW * CC];  // LN output lo bf16
__device__ __nv_bfloat16 g_wh[3 * CC * CC];           // W hi bf16 (wq pre-scaled)
__device__ __nv_bfloat16 g_wl[3 * CC * CC];
// projections, split bf16 interleaved: unit p = channel pair, layout
// [m][p] -> 4 bf16: {hi(2p), hi(2p+1), lo(2p), lo(2p+1)}  (8 bytes per unit)
__device__ __nv_bfloat16 g_qi[(size_t)BB * HW * CC * 2];
__device__ __nv_bfloat16 g_ki[(size_t)BB * HW * CC * 2];
__device__ __nv_bfloat16 g_vi[(size_t)BB * HW * CC * 2];
__device__ float g_acc[(size_t)BB * HW * CC];   // pixel-major accumulator [b][n][c]
__device__ float g_sims[(size_t)BB * SS * TT];
__device__ int   g_idx [(size_t)BB * SS * TT];

// ---------------- zero the accumulator -------------------------------------------
__global__ void zero_kernel() {
    size_t i = ((size_t)blockIdx.x * 256 + threadIdx.x) * 4;
    *(float4*)&g_acc[i] = make_float4(0.f, 0.f, 0.f, 0.f);
}

// ---------------- LayerNorm: x (B,C,H,W) -> split bf16 (B,HW,C) -------------------
__global__ void ln_kernel(const float* __restrict__ x,
                          const float* __restrict__ lnw,
                          const float* __restrict__ lnb) {
    __shared__ float tile[256][33];
    __shared__ float red_s[8][32], red_ss[8][32];
    __shared__ float s_mean[32], s_inv[32];

    int blk = blockIdx.x;            // 1024 blocks, 512 per batch
    int b   = blk >> 9;
    int n0  = (blk & 511) * 32;
    int tid = threadIdx.x;           // 256
    int tn  = tid & 31;
    int cg  = tid >> 5;              // warp id 0..7

    const float* xb = x + (size_t)b * CC * HW;

#pragma unroll 8
    for (int r = 0; r < 32; r++) {
        int c = r * 8 + cg;
        tile[c][tn] = xb[(size_t)c * HW + n0 + tn];
    }
    __syncthreads();

    float s = 0.f, ss = 0.f;
#pragma unroll 8
    for (int j = 0; j < 32; j++) {
        float v = tile[cg * 32 + j][tn];
        s += v; ss += v * v;
    }
    red_s[cg][tn] = s; red_ss[cg][tn] = ss;
    __syncthreads();
    if (cg == 0) {
        float S = 0.f, SSU = 0.f;
#pragma unroll
        for (int j = 0; j < 8; j++) { S += red_s[j][tn]; SSU += red_ss[j][tn]; }
        float m   = S * (1.0f / 256.0f);
        float var = SSU * (1.0f / 256.0f) - m * m;
        s_mean[tn] = m;
        s_inv[tn]  = rsqrtf(var + LN_EPS);
    }
    __syncthreads();

    float wv = lnw[tid], bv = lnb[tid];
    size_t rb = (size_t)(b * HW + n0) * CC + tid;
#pragma unroll 8
    for (int it = 0; it < 32; it++) {
        float v = tile[tid][it];
        float y = (v - s_mean[it]) * s_inv[it] * wv + bv;
        __nv_bfloat16 hi = __float2bfloat16(y);
        g_xh[rb + (size_t)it * CC] = hi;
        g_xl[rb + (size_t)it * CC] = __float2bfloat16(y - __bfloat162float(hi));
    }
}

// ---------------- split weights into bf16 hi/lo (SCALE folded into wq) -----------
__global__ void wsplit_kernel(const float* __restrict__ Wq,
                              const float* __restrict__ Wk,
                              const float* __restrict__ Wv) {
    int i = blockIdx.x * 256 + threadIdx.x;        // 0 .. 3*65536-1
    int mat = i >> 16, j = i & 65535;
    const float* W = (mat == 0) ? Wq : ((mat == 1) ? Wk : Wv);
    float f = W[j];
    if (mat == 0) f *= SCALE;
    __nv_bfloat16 hi = __float2bfloat16(f);
    g_wh[i] = hi;
    g_wl[i] = __float2bfloat16(f - __bfloat162float(hi));
}

// ---------------- projection GEMM on HMMA (mma.sync, split-bf16 3-product) --------
// CTA tile 128x64, 8 warps of 32x32, 2 CTAs/SM. K=256 in 8 chunks of 32.
#define STRA 40                         // smem row stride (bf16 units)
#define GT_SMEM ((2 * 128 * STRA + 2 * 64 * STRA) * 2)   // Ah,Al[128][40] Bh,Bl[64][40]

__global__ void __launch_bounds__(256, 2) gemm_tc_kernel() {
    extern __shared__ __nv_bfloat16 sm_bf[];
    __nv_bfloat16* Ah = sm_bf;
    __nv_bfloat16* Al = Ah + 128 * STRA;
    __nv_bfloat16* Bh = Al + 128 * STRA;
    __nv_bfloat16* Bl = Bh + 64 * STRA;

    int mat = blockIdx.z;
    __nv_bfloat16* Oi = (mat == 0) ? g_qi : ((mat == 1) ? g_ki : g_vi);
    size_t bm = (size_t)blockIdx.x * 128;
    int bn = blockIdx.y * 64;

    int tid = threadIdx.x;
    int wid = tid >> 5, lane = tid & 31;
    int grp = lane >> 2, tig = lane & 3;
    int wm = (wid & 3) * 32, wn = (wid >> 2) * 32;

    const __nv_bfloat16* wh_b = g_wh + (size_t)mat * 65536;
    const __nv_bfloat16* wl_b = g_wl + (size_t)mat * 65536;

    // A loader: 2 threads/row, 32B halves; B loader: 4 threads/row, 16B quarters
    int lrA = tid >> 1, lhA = tid & 1;
    int lrB = tid >> 2, lhB = tid & 3;
    const uint4* pAh = (const uint4*)(g_xh + (bm + lrA) * 256 + lhA * 16);
    const uint4* pAl = (const uint4*)(g_xl + (bm + lrA) * 256 + lhA * 16);
    const uint4* pBh = (const uint4*)(wh_b + (size_t)(bn + lrB) * 256 + lhB * 8);
    const uint4* pBl = (const uint4*)(wl_b + (size_t)(bn + lrB) * 256 + lhB * 8);
    int soffA = lrA * STRA + lhA * 16;
    int soffB = lrB * STRA + lhB * 8;

    float acc[2][4][4];
#pragma unroll
    for (int mi = 0; mi < 2; mi++)
#pragma unroll
        for (int ni = 0; ni < 4; ni++)
#pragma unroll
            for (int rgi = 0; rgi < 4; rgi++) acc[mi][ni][rgi] = 0.f;

    // register prefetch of chunk 0
    uint4 rAh[2], rAl[2], rBh, rBl;
#pragma unroll
    for (int q = 0; q < 2; q++) { rAh[q] = pAh[q]; rAl[q] = pAl[q]; }
    rBh = pBh[0]; rBl = pBl[0];

#pragma unroll 1
    for (int chunk = 0; chunk < 8; chunk++) {
#pragma unroll
        for (int q = 0; q < 2; q++) {
            *(uint4*)(Ah + soffA + q * 8) = rAh[q];
            *(uint4*)(Al + soffA + q * 8) = rAl[q];
        }
        *(uint4*)(Bh + soffB) = rBh;
        *(uint4*)(Bl + soffB) = rBl;
        __syncthreads();

        int nc = (chunk < 7) ? (chunk + 1) : 7;
        int gofs = nc * 4;   // 32 cols = 4 uint4 per row-chunk step
#pragma unroll
        for (int q = 0; q < 2; q++) { rAh[q] = pAh[gofs + q]; rAl[q] = pAl[gofs + q]; }
        rBh = pBh[gofs]; rBl = pBl[gofs];

#pragma unroll
        for (int ks = 0; ks < 32; ks += 16) {
            uint32_t ah[2][4], al[2][4], bh[4][2], bl[4][2];
            int ca = ks + tig * 2;
#pragma unroll
            for (int mi = 0; mi < 2; mi++) {
                int r0 = wm + mi * 16 + grp;
                ah[mi][0] = *(const uint32_t*)(Ah + r0 * STRA + ca);
                ah[mi][1] = *(const uint32_t*)(Ah + (r0 + 8) * STRA + ca);
                ah[mi][2] = *(const uint32_t*)(Ah + r0 * STRA + ca + 8);
                ah[mi][3] = *(const uint32_t*)(Ah + (r0 + 8) * STRA + ca + 8);
                al[mi][0] = *(const uint32_t*)(Al + r0 * STRA + ca);
                al[mi][1] = *(const uint32_t*)(Al + (r0 + 8) * STRA + ca);
                al[mi][2] = *(const uint32_t*)(Al + r0 * STRA + ca + 8);
                al[mi][3] = *(const uint32_t*)(Al + (r0 + 8) * STRA + ca + 8);
            }
#pragma unroll
            for (int ni = 0; ni < 4; ni++) {
                int n0 = wn + ni * 8 + grp;
                bh[ni][0] = *(const uint32_t*)(Bh + n0 * STRA + ca);
                bh[ni][1] = *(const uint32_t*)(Bh + n0 * STRA + ca + 8);
                bl[ni][0] = *(const uint32_t*)(Bl + n0 * STRA + ca);
                bl[ni][1] = *(const uint32_t*)(Bl + n0 * STRA + ca + 8);
            }
#pragma unroll
            for (int mi = 0; mi < 2; mi++)
#pragma unroll
                for (int ni = 0; ni < 4; ni++) {
                    float* c = acc[mi][ni];
                    MMA_BF16(c[0], c[1], c[2], c[3],
                             ah[mi][0], ah[mi][1], ah[mi][2], ah[mi][3],
                             bh[ni][0], bh[ni][1]);
                    MMA_BF16(c[0], c[1], c[2], c[3],
                             ah[mi][0], ah[mi][1], ah[mi][2], ah[mi][3],
                             bl[ni][0], bl[ni][1]);
                    MMA_BF16(c[0], c[1], c[2], c[3],
                             al[mi][0], al[mi][1], al[mi][2], al[mi][3],
                             bh[ni][0], bh[ni][1]);
                }
        }
        __syncthreads();
    }

    // epilogue: interleaved split store — one uint2 per (row, channel-pair)
#pragma unroll
    for (int mi = 0; mi < 2; mi++) {
#pragma unroll
        for (int ni = 0; ni < 4; ni++) {
            float* c = acc[mi][ni];
            size_t row0 = bm + wm + mi * 16 + grp;
            size_t row1 = row0 + 8;
            int col = bn + wn + ni * 8 + tig * 2;   // even channel pair base
            __nv_bfloat16 h0 = __float2bfloat16(c[0]);
            __nv_bfloat16 h1 = __float2bfloat16(c[1]);
            __nv_bfloat16 h2 = __float2bfloat16(c[2]);
            __nv_bfloat16 h3 = __float2bfloat16(c[3]);
            uint2 v0, v1;
            v0.x = pk2(h0, h1);
            v0.y = pk2(__float2bfloat16(c[0] - __bfloat162float(h0)),
                       __float2bfloat16(c[1] - __bfloat162float(h1)));
            v1.x = pk2(h2, h3);
            v1.y = pk2(__float2bfloat16(c[2] - __bfloat162float(h2)),
                       __float2bfloat16(c[3] - __bfloat162float(h3)));
            *(uint2*)&Oi[(row0 * 128 + (col >> 1)) * 4] = v0;
            *(uint2*)&Oi[(row1 * 128 + (col >> 1)) * 4] = v1;
        }
    }
}

// ---------------- top-k: per (b,s) row of 16384, select top-128 (radix select) ----
// 512 threads, 4-way replicated histogram, parallel suffix-scan bin selection.
#define TK_N 16384
#define TK_THR 512
#define TOPK_SMEM ((TK_N + 1024 + 256) * 4)
__global__ void __launch_bounds__(TK_THR) topk_kernel(const float* __restrict__ aff) {
    extern __shared__ unsigned int shm[];
    unsigned int* keys  = shm;               // 16384
    unsigned int* hist  = shm + TK_N;        // 4 copies x 256
    unsigned int* sscan = hist + 1024;       // 256
    __shared__ unsigned int s_prefix, s_rem, s_cntgt, s_cnteq, s_sel, s_gt;
    __shared__ int eq_idx[128];

    int row = blockIdx.x;
    const float* ap = aff + (size_t)row * TK_N;
    int tid = threadIdx.x;
    int hcp = (tid >> 5) & 3;                // histogram copy = warp % 4

    for (int n = tid; n < TK_N; n += TK_THR) {
        unsigned int u = __float_as_uint(ap[n]);
        keys[n] = (u & 0x80000000u) ? ~u : (u | 0x80000000u);
    }
    if (tid == 0) { s_prefix = 0u; s_rem = 128u; s_cntgt = 0u; s_cnteq = 0u; }
    __syncthreads();

    for (int sh = 24; sh >= 0; sh -= 8) {
        for (int i = tid; i < 1024; i += TK_THR) hist[i] = 0u;
        __syncthreads();
        unsigned int pref = s_prefix, rem = s_rem;
        unsigned int mask = (sh == 24) ? 0u : (0xFFFFFFFFu << (sh + 8));
#pragma unroll 8
        for (int n = tid; n < TK_N; n += TK_THR) {
            unsigned int k = keys[n];
            if (((k ^ pref) & mask) == 0u)
                atomicAdd(&hist[hcp * 256 + ((k >> sh) & 0xFF)], 1u);
        }
        __syncthreads();
        if (tid < 256)
            sscan[tid] = hist[tid] + hist[256 + tid] + hist[512 + tid] + hist[768 + tid];
        __syncthreads();
        // suffix sum: sscan[b] = count of keys with byte >= b (within prefix)
#pragma unroll
        for (int off = 1; off < 256; off <<= 1) {
            unsigned int v = 0u, a = 0u;
            if (tid < 256) { v = sscan[tid]; if (tid + off < 256) a = sscan[tid + off]; }
            __syncthreads();
            if (tid < 256) sscan[tid] = v + a;
            __syncthreads();
        }
        if (tid < 256) {
            unsigned int ge = sscan[tid];
            unsigned int gt = (tid < 255) ? sscan[tid + 1] : 0u;
            if (ge >= rem && gt < rem) { s_sel = (unsigned int)tid; s_gt = gt; }
        }
        __syncthreads();
        if (tid == 0) {
            s_prefix = pref | (s_sel << sh);
            s_rem = rem - s_gt;
        }
        __syncthreads();
    }

    unsigned int thr = s_prefix;
    int take_eq = (int)s_rem;
    int n_gt = 128 - take_eq;

    for (int n = tid; n < TK_N; n += TK_THR) {
        unsigned int k = keys[n];
        if (k > thr) {
            int p = (int)atomicAdd(&s_cntgt, 1u);
            g_idx[(size_t)row * 128 + p]  = n;
            g_sims[(size_t)row * 128 + p] = ap[n];
        } else if (k == thr) {
            int e = (int)atomicAdd(&s_cnteq, 1u);
            if (e < 128) eq_idx[e] = n;
        }
    }
    __syncthreads();
    if (tid == 0) {
        int ne = (int)s_cnteq; if (ne > 128) ne = 128;
        // sort ascending so ties break toward lowest index (matches lax.top_k)
        for (int i = 1; i < ne; i++) {
            int v = eq_idx[i]; int j = i - 1;
            while (j >= 0 && eq_idx[j] > v) { eq_idx[j + 1] = eq_idx[j]; j--; }
            eq_idx[j + 1] = v;
        }
        for (int i = 0; i < take_eq; i++) {
            int src = (i < ne) ? i : (ne - 1);
            int n = eq_idx[src];
            g_idx[(size_t)row * 128 + n_gt + i]  = n;
            g_sims[(size_t)row * 128 + n_gt + i] = ap[n];
        }
    }
}

// ---------------- attention per (head, s, b) — HMMA split-bf16 --------------------
// smem bf16: qh/ql/kh/kl [128][40], vh/vl transposed [32][136]; + sims/idx
#define QSTR 40
#define VSTR 136
#define SM_QH 0
#define SM_QL (SM_QH + 128 * QSTR)
#define SM_KH (SM_QL + 128 * QSTR)
#define SM_KL (SM_KH + 128 * QSTR)
#define SM_VH (SM_KL + 128 * QSTR)
#define SM_VL (SM_VH + 32 * VSTR)
#define SM_BF_END (SM_VL + 32 * VSTR)
#define ATTN_SMEM (SM_BF_END * 2 + 128 * 8)

__global__ void __launch_bounds__(256) attn_kernel() {
    extern __shared__ __nv_bfloat16 abf[];
    __nv_bfloat16* qh = abf + SM_QH;
    __nv_bfloat16* ql = abf + SM_QL;
    __nv_bfloat16* kh = abf + SM_KH;
    __nv_bfloat16* kl = abf + SM_KL;
    __nv_bfloat16* vh = abf + SM_VH;   // [c][u]
    __nv_bfloat16* vl = abf + SM_VL;
    float* sims_s = (float*)(abf + SM_BF_END);
    int*   idx_s  = (int*)(sims_s + 128);

    int h = blockIdx.x, s = blockIdx.y, b = blockIdx.z;
    int tid = threadIdx.x;              // 256
    int wid = tid >> 5, lane = tid & 31;
    int grp = lane >> 2, tig = lane & 3;
    int wm = wid * 16;
    int base = ((b << 8) + s) << 7;

    if (tid < 128) {
        idx_s[tid]  = g_idx[base + tid];
        sims_s[tid] = g_sims[base + tid];
    }
    __syncthreads();

    int coff = h * DH;
    // gather: 3x 16B loads per (u, 4ch); interleaved layout -> register unpack
    for (int i = tid; i < 1024; i += 256) {
        int u = i >> 3, c = (i & 7) * 4;
        size_t unit = ((size_t)(b * HW + idx_s[u])) * 128 + ((coff + c) >> 1);
        uint4 vq = *(const uint4*)&g_qi[unit * 4];
        uint4 vk = *(const uint4*)&g_ki[unit * 4];
        uint4 vv = *(const uint4*)&g_vi[unit * 4];
        // .x = hi(c,c+1) .y = lo(c,c+1) .z = hi(c+2,c+3) .w = lo(c+2,c+3)
        *(uint2*)&qh[u * QSTR + c] = make_uint2(vq.x, vq.z);
        *(uint2*)&ql[u * QSTR + c] = make_uint2(vq.y, vq.w);
        *(uint2*)&kh[u * QSTR + c] = make_uint2(vk.x, vk.z);
        *(uint2*)&kl[u * QSTR + c] = make_uint2(vk.y, vk.w);
        __nv_bfloat16 th[4], tl[4];
        *(uint32_t*)&th[0] = vv.x; *(uint32_t*)&th[2] = vv.z;
        *(uint32_t*)&tl[0] = vv.y; *(uint32_t*)&tl[2] = vv.w;
#pragma unroll
        for (int j = 0; j < 4; j++) {
            vh[(c + j) * VSTR + u] = th[j];
            vl[(c + j) * VSTR + u] = tl[j];
        }
    }
    __syncthreads();

    // GEMM1: S[wm+.., 128] = Q·K^T (3-product split), acc[16 n-tiles][4]
    float acc[16][4];
#pragma unroll
    for (int nt = 0; nt < 16; nt++)
#pragma unroll
        for (int rgi = 0; rgi < 4; rgi++) acc[nt][rgi] = 0.f;

#pragma unroll
    for (int ks = 0; ks < 2; ks++) {
        int ca = ks * 16 + tig * 2;
        uint32_t ah0 = *(const uint32_t*)&qh[(wm + grp) * QSTR + ca];
        uint32_t ah1 = *(const uint32_t*)&qh[(wm + grp + 8) * QSTR + ca];
        uint32_t ah2 = *(const uint32_t*)&qh[(wm + grp) * QSTR + ca + 8];
        uint32_t ah3 = *(const uint32_t*)&qh[(wm + grp + 8) * QSTR + ca + 8];
        uint32_t al0 = *(const uint32_t*)&ql[(wm + grp) * QSTR + ca];
        uint32_t al1 = *(const uint32_t*)&ql[(wm + grp + 8) * QSTR + ca];
        uint32_t al2 = *(const uint32_t*)&ql[(wm + grp) * QSTR + ca + 8];
        uint32_t al3 = *(const uint32_t*)&ql[(wm + grp + 8) * QSTR + ca + 8];
#pragma unroll
        for (int nt = 0; nt < 16; nt++) {
            int ro = (nt * 8 + grp) * QSTR + ca;
            uint32_t bh0 = *(const uint32_t*)&kh[ro];
            uint32_t bh1 = *(const uint32_t*)&kh[ro + 8];
            uint32_t bl0 = *(const uint32_t*)&kl[ro];
            uint32_t bl1 = *(const uint32_t*)&kl[ro + 8];
            float* c = acc[nt];
            MMA_BF16(c[0], c[1], c[2], c[3], ah0, ah1, ah2, ah3, bh0, bh1);
            MMA_BF16(c[0], c[1], c[2], c[3], ah0, ah1, ah2, ah3, bl0, bl1);
            MMA_BF16(c[0], c[1], c[2], c[3], al0, al1, al2, al3, bh0, bh1);
        }
    }

    // softmax in registers: rows wm+grp (c0,c1) and wm+grp+8 (c2,c3)
    float mx0 = -3.4e38f, mx1 = -3.4e38f;
#pragma unroll
    for (int nt = 0; nt < 16; nt++) {
        mx0 = fmaxf(mx0, fmaxf(acc[nt][0], acc[nt][1]));
        mx1 = fmaxf(mx1, fmaxf(acc[nt][2], acc[nt][3]));
    }
#pragma unroll
    for (int m = 1; m <= 2; m <<= 1) {
        mx0 = fmaxf(mx0, __shfl_xor_sync(0xffffffffu, mx0, m));
        mx1 = fmaxf(mx1, __shfl_xor_sync(0xffffffffu, mx1, m));
    }
    float sum0 = 0.f, sum1 = 0.f;
#pragma unroll
    for (int nt = 0; nt < 16; nt++) {
        acc[nt][0] = __expf(acc[nt][0] - mx0);
        acc[nt][1] = __expf(acc[nt][1] - mx0);
        acc[nt][2] = __expf(acc[nt][2] - mx1);
        acc[nt][3] = __expf(acc[nt][3] - mx1);
        sum0 += acc[nt][0] + acc[nt][1];
        sum1 += acc[nt][2] + acc[nt][3];
    }
#pragma unroll
    for (int m = 1; m <= 2; m <<= 1) {
        sum0 += __shfl_xor_sync(0xffffffffu, sum0, m);
        sum1 += __shfl_xor_sync(0xffffffffu, sum1, m);
    }

    // GEMM2: O = (P .* sims[u]) · V, P from acc regs (sims folded per-column)
    float ot[4][4];
#pragma unroll
    for (int nt = 0; nt < 4; nt++)
#pragma unroll
        for (int rgi = 0; rgi < 4; rgi++) ot[nt][rgi] = 0.f;

#pragma unroll
    for (int ks = 0; ks < 8; ks++) {
        float* t0 = acc[2 * ks];
        float* t1 = acc[2 * ks + 1];
        float w00 = sims_s[ks * 16 + tig * 2];
        float w01 = sims_s[ks * 16 + tig * 2 + 1];
        float w10 = sims_s[ks * 16 + 8 + tig * 2];
        float w11 = sims_s[ks * 16 + 8 + tig * 2 + 1];
        float p00 = t0[0] * w00, p01 = t0[1] * w01;
        float p02 = t0[2] * w00, p03 = t0[3] * w01;
        float p10 = t1[0] * w10, p11 = t1[1] * w11;
        float p12 = t1[2] * w10, p13 = t1[3] * w11;
        __nv_bfloat16 h00 = __float2bfloat16(p00), h01 = __float2bfloat16(p01);
        __nv_bfloat16 h02 = __float2bfloat16(p02), h03 = __float2bfloat16(p03);
        __nv_bfloat16 h10 = __float2bfloat16(p10), h11 = __float2bfloat16(p11);
        __nv_bfloat16 h12 = __float2bfloat16(p12), h13 = __float2bfloat16(p13);
        uint32_t ah0 = pk2(h00, h01), ah1 = pk2(h02, h03);
        uint32_t ah2 = pk2(h10, h11), ah3 = pk2(h12, h13);
        uint32_t al0 = pk2(__float2bfloat16(p00 - __bfloat162float(h00)),
                           __float2bfloat16(p01 - __bfloat162float(h01)));
        uint32_t al1 = pk2(__float2bfloat16(p02 - __bfloat162float(h02)),
                           __float2bfloat16(p03 - __bfloat162float(h03)));
        uint32_t al2 = pk2(__float2bfloat16(p10 - __bfloat162float(h10)),
                           __float2bfloat16(p11 - __bfloat162float(h11)));
        uint32_t al3 = pk2(__float2bfloat16(p12 - __bfloat162float(h12)),
                           __float2bfloat16(p13 - __bfloat162float(h13)));
        int ub = ks * 16 + tig * 2;
#pragma unroll
        for (int nt = 0; nt < 4; nt++) {
            int bo = (nt * 8 + grp) * VSTR + ub;
            uint32_t bh0 = *(const uint32_t*)&vh[bo];
            uint32_t bh1 = *(const uint32_t*)&vh[bo + 8];
            uint32_t bl0 = *(const uint32_t*)&vl[bo];
            uint32_t bl1 = *(const uint32_t*)&vl[bo + 8];
            float* c = ot[nt];
            MMA_BF16(c[0], c[1], c[2], c[3], ah0, ah1, ah2, ah3, bh0, bh1);
            MMA_BF16(c[0], c[1], c[2], c[3], ah0, ah1, ah2, ah3, bl0, bl1);
            MMA_BF16(c[0], c[1], c[2], c[3], al0, al1, al2, al3, bh0, bh1);
        }
    }

    // scatter with row scale sims/sum -> pixel-major accumulator (coalesced sectors)
    {
        int r0 = wm + grp, r1 = wm + grp + 8;
        float rs0 = sims_s[r0] / sum0;
        float rs1 = sims_s[r1] / sum1;
        size_t n0 = (size_t)(b * HW + idx_s[r0]) * 256 + coff;
        size_t n1 = (size_t)(b * HW + idx_s[r1]) * 256 + coff;
#pragma unroll
        for (int nt = 0; nt < 4; nt++) {
            int c0 = nt * 8 + tig * 2;
            atomicAdd(&g_acc[n0 + c0],     ot[nt][0] * rs0);
            atomicAdd(&g_acc[n0 + c0 + 1], ot[nt][1] * rs0);
            atomicAdd(&g_acc[n1 + c0],     ot[nt][2] * rs1);
            atomicAdd(&g_acc[n1 + c0 + 1], ot[nt][3] * rs1);
        }
    }
}

// ---------------- final: out[b][c][n] = g_acc[b][n][c] + v(n,c) -------------------
__global__ void final_kernel(float* __restrict__ out) {
    __shared__ float t[32][33];
    int n0 = blockIdx.x * 32, c0 = blockIdx.y * 32, b = blockIdx.z;
    int tx = threadIdx.x;   // 0..7  channel quad (read phase)
    int ty = threadIdx.y;   // 0..31 row (read phase)

    size_t roff = (size_t)(b * HW + n0 + ty);
    int c = c0 + tx * 4;
    uint4 vv = *(const uint4*)&g_vi[(roff * 128 + (c >> 1)) * 4];
    float4 av = *(const float4*)&g_acc[roff * 256 + c];
    __nv_bfloat16 th[4], tl[4];
    *(uint32_t*)&th[0] = vv.x; *(uint32_t*)&th[2] = vv.z;
    *(uint32_t*)&tl[0] = vv.y; *(uint32_t*)&tl[2] = vv.w;
    t[tx * 4 + 0][ty] = av.x + __bfloat162float(th[0]) + __bfloat162float(tl[0]);
    t[tx * 4 + 1][ty] = av.y + __bfloat162float(th[1]) + __bfloat162float(tl[1]);
    t[tx * 4 + 2][ty] = av.z + __bfloat162float(th[2]) + __bfloat162float(tl[2]);
    t[tx * 4 + 3][ty] = av.w + __bfloat162float(th[3]) + __bfloat162float(tl[3]);
    __syncthreads();

    int tid = ty * 8 + tx;
    int wtx = tid & 31, wty = tid >> 5;   // n offset, c group
#pragma unroll
    for (int j = wty; j < 32; j += 8)
        out[((size_t)b * CC + c0 + j) * HW + n0 + wtx] = t[j][wtx];
}

// ---------------- launch ----------------
extern "C" void kernel_launch(void* const* d_in, const int* in_sizes, int n_in,
                              void* d_out, int out_size) {
    const float* x   = (const float*)d_in[0];
    const float* aff = (const float*)d_in[1];
    const float* lnw = (const float*)d_in[2];
    const float* lnb = (const float*)d_in[3];
    const float* wq  = (const float*)d_in[4];
    const float* wk  = (const float*)d_in[5];
    const float* wv  = (const float*)d_in[6];
    float* out = (float*)d_out;

    cudaFuncSetAttribute(topk_kernel, cudaFuncAttributeMaxDynamicSharedMemorySize, TOPK_SMEM);
    cudaFuncSetAttribute(attn_kernel, cudaFuncAttributeMaxDynamicSharedMemorySize, ATTN_SMEM);
    cudaFuncSetAttribute(gemm_tc_kernel, cudaFuncAttributeMaxDynamicSharedMemorySize, GT_SMEM);

    zero_kernel<<<(BB * HW * CC) / (256 * 4), 256>>>();
    ln_kernel<<<1024, 256>>>(x, lnw, lnb);
    wsplit_kernel<<<768, 256>>>(wq, wk, wv);
    gemm_tc_kernel<<<dim3(256, 4, 3), 256, GT_SMEM>>>();
    topk_kernel<<<BB * SS, TK_THR, TOPK_SMEM>>>(aff);
    attn_kernel<<<dim3(NH, SS, BB), 256, ATTN_SMEM>>>();
    final_kernel<<<dim3(HW / 32, CC / 32, BB), dim3(8, 32)>>>(out);
}